// round 5
// baseline (speedup 1.0000x reference)
#include <cuda_runtime.h>

#define Nn 50000
#define Ee 800000
#define Hh 64
#define Ll 4
#define Gg 500
#define Cc 10
#define BN_EPS 1e-5f

// ---------------- device scratch (static, 16B-aligned) ----------------
__device__ __align__(16) float g_h[(size_t)Ll * Nn * Hh]; // per-layer outputs (gather source)
__device__ __align__(16) float g_W1[Ll * Hh * Hh];
__device__ __align__(16) float g_W2[Ll * Hh * Hh];
__device__ __align__(16) float g_c1[Ll * Hh];
__device__ __align__(16) float g_c2[Ll * Hh];
__device__ __align__(16) float g_pool[Gg * Ll * Hh];
// CSR by destination
__device__ int g_cnt[Nn + 1];
__device__ int g_indptr[Nn + 1];
__device__ int g_cursor[Nn];
__device__ int g_idx[Ee];

// ---------------- zero pool + counts ----------------
__global__ void zero_k() {
    int t = blockIdx.x * blockDim.x + threadIdx.x;
    const int tot_pool = Gg * Ll * Hh / 4;
    if (t < tot_pool)
        reinterpret_cast<float4*>(g_pool)[t] = make_float4(0.f, 0.f, 0.f, 0.f);
    if (t < Nn + 1) g_cnt[t] = 0;
}

// ---------------- fold BN into weights/bias ----------------
__global__ void fold_k(const float* __restrict__ W1, const float* __restrict__ b1,
                       const float* __restrict__ g1, const float* __restrict__ be1,
                       const float* __restrict__ m1, const float* __restrict__ v1,
                       const float* __restrict__ W2, const float* __restrict__ b2,
                       const float* __restrict__ g2, const float* __restrict__ be2,
                       const float* __restrict__ m2, const float* __restrict__ v2) {
    int idx = blockIdx.x * blockDim.x + threadIdx.x;
    if (idx >= Ll * Hh * Hh) return;
    int j = idx & (Hh - 1);
    int lk = idx >> 6;
    int l = lk >> 6;
    int k = lk & 63;
    int lj = l * Hh + j;
    float s1 = g1[lj] * rsqrtf(v1[lj] + BN_EPS);
    float s2 = g2[lj] * rsqrtf(v2[lj] + BN_EPS);
    g_W1[idx] = W1[idx] * s1;
    g_W2[idx] = W2[idx] * s2;
    if (k == 0) {
        g_c1[lj] = b1[lj] * s1 + be1[lj] - m1[lj] * s1;
        g_c2[lj] = b2[lj] * s2 + be2[lj] - m2[lj] * s2;
    }
}

// ---------------- CSR build: histogram / scan / fill ----------------
__global__ void hist_k(const int* __restrict__ ei) {
    int e = blockIdx.x * blockDim.x + threadIdx.x;
    if (e < Ee) atomicAdd(g_cnt + __ldg(ei + Ee + e), 1);
}

__global__ void scan_k() {
    __shared__ int part[1024];
    int t = threadIdx.x;
    const int CH = 49;  // 1024*49 = 50176 >= 50001
    int s0 = t * CH;
    int sum = 0;
    for (int i = 0; i < CH; i++) {
        int idx = s0 + i;
        if (idx < Nn + 1) sum += g_cnt[idx];
    }
    part[t] = sum;
    __syncthreads();
    for (int off = 1; off < 1024; off <<= 1) {
        int v = (t >= off) ? part[t - off] : 0;
        __syncthreads();
        part[t] += v;
        __syncthreads();
    }
    int run = (t == 0) ? 0 : part[t - 1];
    for (int i = 0; i < CH; i++) {
        int idx = s0 + i;
        if (idx < Nn + 1) {
            g_indptr[idx] = run;
            if (idx < Nn) g_cursor[idx] = run;
            run += g_cnt[idx];
        }
    }
}

__global__ void fill_k(const int* __restrict__ ei) {
    int e = blockIdx.x * blockDim.x + threadIdx.x;
    if (e >= Ee) return;
    int s = __ldg(ei + e);
    int d = __ldg(ei + Ee + e);
    int pos = atomicAdd(g_cursor + d, 1);
    g_idx[pos] = s;
}

// ---------------- fused gather + GIN MLP + pool-red ----------------
// Block handles 64 rows. Phase 1: warp-per-8-rows CSR gather of
// z = h_self + sum_in_neighbors into smem. Phase 2: 2x fused GEMM (BN folded).
// Epilogue: write hout (layers 0..2) and red y into g_pool[batch[row]].
__global__ void __launch_bounds__(256, 5) mlp_k(const float* __restrict__ hin,
                                                float* __restrict__ hout,
                                                const int* __restrict__ batch,
                                                int layer, int write_h) {
    __shared__ __align__(16) float sZ[64][68];
    __shared__ __align__(16) float sW[64 * 64];

    int tid = threadIdx.x;
    int row0 = blockIdx.x * 64;
    int wid = tid >> 5;
    int lane = tid & 31;

    // ---- gather phase: each warp handles 8 rows serially, lane owns 2 cols ----
    for (int rr = 0; rr < 8; rr++) {
        int r = wid * 8 + rr;
        int gr = row0 + r;
        float2 acc = make_float2(0.f, 0.f);
        if (gr < Nn) {
            acc = *reinterpret_cast<const float2*>(hin + (size_t)gr * Hh + 2 * lane); // self
            int e = __ldg(g_indptr + gr);
            int end = __ldg(g_indptr + gr + 1);
            // 4-wide unrolled prefetch for MLP
            for (; e + 4 <= end; e += 4) {
                int s0 = __ldg(g_idx + e);
                int s1 = __ldg(g_idx + e + 1);
                int s2 = __ldg(g_idx + e + 2);
                int s3 = __ldg(g_idx + e + 3);
                float2 v0 = *reinterpret_cast<const float2*>(hin + (size_t)s0 * Hh + 2 * lane);
                float2 v1 = *reinterpret_cast<const float2*>(hin + (size_t)s1 * Hh + 2 * lane);
                float2 v2 = *reinterpret_cast<const float2*>(hin + (size_t)s2 * Hh + 2 * lane);
                float2 v3 = *reinterpret_cast<const float2*>(hin + (size_t)s3 * Hh + 2 * lane);
                acc.x += v0.x + v1.x + v2.x + v3.x;
                acc.y += v0.y + v1.y + v2.y + v3.y;
            }
            for (; e < end; e++) {
                int s = __ldg(g_idx + e);
                float2 v = *reinterpret_cast<const float2*>(hin + (size_t)s * Hh + 2 * lane);
                acc.x += v.x; acc.y += v.y;
            }
        }
        *reinterpret_cast<float2*>(&sZ[r][2 * lane]) = acc;
    }
    // load W1'
    {
        const float* Wg = g_W1 + layer * Hh * Hh;
        for (int i = tid * 4; i < 4096; i += 1024)
            *reinterpret_cast<float4*>(sW + i) = *reinterpret_cast<const float4*>(Wg + i);
    }
    __syncthreads();

    int tx = tid & 15;
    int ty = tid >> 4;

    float acc[4][4];
    #pragma unroll
    for (int i = 0; i < 4; i++)
        #pragma unroll
        for (int j = 0; j < 4; j++) acc[i][j] = 0.f;

    // GEMM1
    #pragma unroll
    for (int k0 = 0; k0 < 64; k0 += 4) {
        float za[4][4];
        #pragma unroll
        for (int i = 0; i < 4; i++) {
            float4 z4 = *reinterpret_cast<const float4*>(&sZ[ty * 4 + i][k0]);
            za[i][0] = z4.x; za[i][1] = z4.y; za[i][2] = z4.z; za[i][3] = z4.w;
        }
        #pragma unroll
        for (int kk = 0; kk < 4; kk++) {
            float4 w = *reinterpret_cast<const float4*>(sW + (k0 + kk) * 64 + tx * 4);
            #pragma unroll
            for (int i = 0; i < 4; i++) {
                acc[i][0] = fmaf(za[i][kk], w.x, acc[i][0]);
                acc[i][1] = fmaf(za[i][kk], w.y, acc[i][1]);
                acc[i][2] = fmaf(za[i][kk], w.z, acc[i][2]);
                acc[i][3] = fmaf(za[i][kk], w.w, acc[i][3]);
            }
        }
    }
    float4 c1v = *reinterpret_cast<const float4*>(g_c1 + layer * Hh + tx * 4);
    __syncthreads();

    // y1 = relu(acc + c1) -> sZ; reload sW with W2'
    #pragma unroll
    for (int i = 0; i < 4; i++) {
        float4 y;
        y.x = fmaxf(acc[i][0] + c1v.x, 0.f);
        y.y = fmaxf(acc[i][1] + c1v.y, 0.f);
        y.z = fmaxf(acc[i][2] + c1v.z, 0.f);
        y.w = fmaxf(acc[i][3] + c1v.w, 0.f);
        *reinterpret_cast<float4*>(&sZ[ty * 4 + i][tx * 4]) = y;
    }
    {
        const float* Wg = g_W2 + layer * Hh * Hh;
        for (int i = tid * 4; i < 4096; i += 1024)
            *reinterpret_cast<float4*>(sW + i) = *reinterpret_cast<const float4*>(Wg + i);
    }
    __syncthreads();

    #pragma unroll
    for (int i = 0; i < 4; i++)
        #pragma unroll
        for (int j = 0; j < 4; j++) acc[i][j] = 0.f;

    // GEMM2
    #pragma unroll
    for (int k0 = 0; k0 < 64; k0 += 4) {
        float za[4][4];
        #pragma unroll
        for (int i = 0; i < 4; i++) {
            float4 z4 = *reinterpret_cast<const float4*>(&sZ[ty * 4 + i][k0]);
            za[i][0] = z4.x; za[i][1] = z4.y; za[i][2] = z4.z; za[i][3] = z4.w;
        }
        #pragma unroll
        for (int kk = 0; kk < 4; kk++) {
            float4 w = *reinterpret_cast<const float4*>(sW + (k0 + kk) * 64 + tx * 4);
            #pragma unroll
            for (int i = 0; i < 4; i++) {
                acc[i][0] = fmaf(za[i][kk], w.x, acc[i][0]);
                acc[i][1] = fmaf(za[i][kk], w.y, acc[i][1]);
                acc[i][2] = fmaf(za[i][kk], w.z, acc[i][2]);
                acc[i][3] = fmaf(za[i][kk], w.w, acc[i][3]);
            }
        }
    }
    float4 c2v = *reinterpret_cast<const float4*>(g_c2 + layer * Hh + tx * 4);
    #pragma unroll
    for (int i = 0; i < 4; i++) {
        int gr = row0 + ty * 4 + i;
        if (gr < Nn) {
            float4 y;
            y.x = fmaxf(acc[i][0] + c2v.x, 0.f);
            y.y = fmaxf(acc[i][1] + c2v.y, 0.f);
            y.z = fmaxf(acc[i][2] + c2v.z, 0.f);
            y.w = fmaxf(acc[i][3] + c2v.w, 0.f);
            if (write_h)
                *reinterpret_cast<float4*>(hout + (size_t)gr * Hh + tx * 4) = y;
            // fused JK-cat sum-pool: pool[batch[gr]][layer*64 + tx*4 ..] += y
            int b = __ldg(batch + gr);
            float* pp = g_pool + (size_t)b * (Ll * Hh) + layer * Hh + tx * 4;
            asm volatile("red.global.add.v4.f32 [%0], {%1,%2,%3,%4};"
                         :: "l"(pp), "f"(y.x), "f"(y.y), "f"(y.z), "f"(y.w) : "memory");
        }
    }
}

// ---------------- head: relu(pooled @ lin1 + b1) @ lin2 + b2 ----------------
__global__ void final_k(const float* __restrict__ W1, const float* __restrict__ b1,
                        const float* __restrict__ W2, const float* __restrict__ b2,
                        float* __restrict__ out) {
    int g = blockIdx.x;
    int j = threadIdx.x;   // 64 threads
    __shared__ float sp[Ll * Hh];
    __shared__ float sh[Hh];
    for (int i = j; i < Ll * Hh; i += 64) sp[i] = g_pool[(size_t)g * (Ll * Hh) + i];
    __syncthreads();
    float a = b1[j];
    #pragma unroll 8
    for (int k = 0; k < Ll * Hh; k++) a = fmaf(sp[k], W1[k * Hh + j], a);
    sh[j] = fmaxf(a, 0.f);
    __syncthreads();
    if (j < Cc) {
        float o = b2[j];
        #pragma unroll
        for (int k = 0; k < Hh; k++) o = fmaf(sh[k], W2[k * Cc + j], o);
        out[g * Cc + j] = o;
    }
}

// ---------------- launch ----------------
extern "C" void kernel_launch(void* const* d_in, const int* in_sizes, int n_in,
                              void* d_out, int out_size) {
    const float* x     = (const float*)d_in[0];
    const int*   ei    = (const int*)d_in[1];
    const int*   batch = (const int*)d_in[2];
    const float* cW1 = (const float*)d_in[3];
    const float* cb1 = (const float*)d_in[4];
    const float* g1  = (const float*)d_in[5];
    const float* be1 = (const float*)d_in[6];
    const float* m1  = (const float*)d_in[7];
    const float* v1  = (const float*)d_in[8];
    const float* cW2 = (const float*)d_in[9];
    const float* cb2 = (const float*)d_in[10];
    const float* g2  = (const float*)d_in[11];
    const float* be2 = (const float*)d_in[12];
    const float* m2  = (const float*)d_in[13];
    const float* v2  = (const float*)d_in[14];
    const float* l1W = (const float*)d_in[15];
    const float* l1b = (const float*)d_in[16];
    const float* l2W = (const float*)d_in[17];
    const float* l2b = (const float*)d_in[18];
    float* out = (float*)d_out;

    zero_k<<<(Nn + 256) / 256, 256>>>();   // pool + cnt (pool smaller than Nn+1 grid covers both)
    fold_k<<<(Ll * Hh * Hh + 255) / 256, 256>>>(cW1, cb1, g1, be1, m1, v1,
                                                cW2, cb2, g2, be2, m2, v2);
    hist_k<<<(Ee + 255) / 256, 256>>>(ei);
    scan_k<<<1, 1024>>>();
    fill_k<<<(Ee + 255) / 256, 256>>>(ei);

    float* hbase;
    cudaGetSymbolAddress((void**)&hbase, g_h);

    const float* hin = x;
    for (int l = 0; l < Ll; l++) {
        float* hout = hbase + (size_t)l * Nn * Hh;
        mlp_k<<<(Nn + 63) / 64, 256>>>(hin, hout, batch, l, l < Ll - 1 ? 1 : 0);
        hin = hout;
    }
    final_k<<<Gg, 64>>>(l1W, l1b, l2W, l2b, out);
}

// round 6
// speedup vs baseline: 1.3090x; 1.3090x over previous
#include <cuda_runtime.h>

#define Nn 50000
#define Ee 800000
#define Hh 64
#define Ll 4
#define Gg 500
#define Cc 10
#define BN_EPS 1e-5f
#define NCHUNK 49   // ceil((Nn+1)/1024)

// ---------------- device scratch (static, 16B-aligned) ----------------
__device__ __align__(16) float g_h[(size_t)Ll * Nn * Hh]; // per-layer outputs (gather source)
__device__ __align__(16) float g_W1[Ll * Hh * Hh];
__device__ __align__(16) float g_W2[Ll * Hh * Hh];
__device__ __align__(16) float g_c1[Ll * Hh];
__device__ __align__(16) float g_c2[Ll * Hh];
__device__ __align__(16) float g_pool[Gg * Ll * Hh];
// CSR by destination
__device__ int g_cnt[Nn + 1];
__device__ int g_indptr[Nn + 1];
__device__ int g_cursor[Nn];
__device__ int g_idx[Ee];
__device__ int g_bsum[NCHUNK];
__device__ int g_boff[NCHUNK];

// ---------------- zero pool + counts ----------------
__global__ void zero_k() {
    int t = blockIdx.x * blockDim.x + threadIdx.x;
    const int tot_pool = Gg * Ll * Hh / 4;
    if (t < tot_pool)
        reinterpret_cast<float4*>(g_pool)[t] = make_float4(0.f, 0.f, 0.f, 0.f);
    if (t < Nn + 1) g_cnt[t] = 0;
}

// ---------------- fold BN into weights/bias ----------------
__global__ void fold_k(const float* __restrict__ W1, const float* __restrict__ b1,
                       const float* __restrict__ g1, const float* __restrict__ be1,
                       const float* __restrict__ m1, const float* __restrict__ v1,
                       const float* __restrict__ W2, const float* __restrict__ b2,
                       const float* __restrict__ g2, const float* __restrict__ be2,
                       const float* __restrict__ m2, const float* __restrict__ v2) {
    int idx = blockIdx.x * blockDim.x + threadIdx.x;
    if (idx >= Ll * Hh * Hh) return;
    int j = idx & (Hh - 1);
    int lk = idx >> 6;
    int l = lk >> 6;
    int k = lk & 63;
    int lj = l * Hh + j;
    float s1 = g1[lj] * rsqrtf(v1[lj] + BN_EPS);
    float s2 = g2[lj] * rsqrtf(v2[lj] + BN_EPS);
    g_W1[idx] = W1[idx] * s1;
    g_W2[idx] = W2[idx] * s2;
    if (k == 0) {
        g_c1[lj] = b1[lj] * s1 + be1[lj] - m1[lj] * s1;
        g_c2[lj] = b2[lj] * s2 + be2[lj] - m2[lj] * s2;
    }
}

// ---------------- CSR build ----------------
__global__ void hist_k(const int* __restrict__ ei) {
    int e = blockIdx.x * blockDim.x + threadIdx.x;
    if (e < Ee) atomicAdd(g_cnt + __ldg(ei + Ee + e), 1);
}

// pass A: per-chunk sums (coalesced, shfl reduce)
__global__ void scanA_k() {
    __shared__ int wsum[32];
    int t = threadIdx.x;
    int idx = blockIdx.x * 1024 + t;
    int v = (idx < Nn + 1) ? g_cnt[idx] : 0;
    #pragma unroll
    for (int off = 16; off > 0; off >>= 1)
        v += __shfl_down_sync(0xffffffffu, v, off);
    if ((t & 31) == 0) wsum[t >> 5] = v;
    __syncthreads();
    if (t < 32) {
        int s = wsum[t];
        #pragma unroll
        for (int off = 16; off > 0; off >>= 1)
            s += __shfl_down_sync(0xffffffffu, s, off);
        if (t == 0) g_bsum[blockIdx.x] = s;
    }
}

// pass B: scan the NCHUNK chunk sums (exclusive), 1 warp
__global__ void scanB_k() {
    int t = threadIdx.x;  // 64 threads; use NCHUNK of them
    int v = (t < NCHUNK) ? g_bsum[t] : 0;
    // inclusive scan across 64 lanes via 2 warps in smem (simple serial would also do)
    __shared__ int s[64];
    s[t] = v;
    __syncthreads();
    for (int off = 1; off < 64; off <<= 1) {
        int a = (t >= off) ? s[t - off] : 0;
        __syncthreads();
        s[t] += a;
        __syncthreads();
    }
    if (t < NCHUNK) g_boff[t] = (t == 0) ? 0 : s[t - 1];
}

// pass C: block exclusive scan + chunk offset -> indptr/cursor
__global__ void scanC_k() {
    __shared__ int wsum[32];
    int t = threadIdx.x;
    int lane = t & 31;
    int wid = t >> 5;
    int idx = blockIdx.x * 1024 + t;
    int v = (idx < Nn + 1) ? g_cnt[idx] : 0;
    // warp inclusive scan
    int incl = v;
    #pragma unroll
    for (int off = 1; off < 32; off <<= 1) {
        int n = __shfl_up_sync(0xffffffffu, incl, off);
        if (lane >= off) incl += n;
    }
    if (lane == 31) wsum[wid] = incl;
    __syncthreads();
    if (t < 32) {
        int s = wsum[t];
        #pragma unroll
        for (int off = 1; off < 32; off <<= 1) {
            int n = __shfl_up_sync(0xffffffffu, s, off);
            if (t >= off) s += n;
        }
        wsum[t] = s;
    }
    __syncthreads();
    int excl = incl - v + (wid > 0 ? wsum[wid - 1] : 0) + g_boff[blockIdx.x];
    if (idx < Nn + 1) {
        g_indptr[idx] = excl;
        if (idx < Nn) g_cursor[idx] = excl;
    }
}

__global__ void fill_k(const int* __restrict__ ei) {
    int e = blockIdx.x * blockDim.x + threadIdx.x;
    if (e >= Ee) return;
    int s = __ldg(ei + e);
    int d = __ldg(ei + Ee + e);
    int pos = atomicAdd(g_cursor + d, 1);
    g_idx[pos] = s;
}

// ---------------- fused gather + GIN MLP + pool-red ----------------
__global__ void __launch_bounds__(256, 5) mlp_k(const float* __restrict__ hin,
                                                float* __restrict__ hout,
                                                const int* __restrict__ batch,
                                                int layer, int write_h) {
    __shared__ __align__(16) float sZ[64][68];
    __shared__ __align__(16) float sW[64 * 64];

    int tid = threadIdx.x;
    int row0 = blockIdx.x * 64;
    int wid = tid >> 5;
    int lane = tid & 31;

    // ---- gather phase: warp per 8 rows, lane owns 2 cols ----
    for (int rr = 0; rr < 8; rr++) {
        int r = wid * 8 + rr;
        int gr = row0 + r;
        float2 acc = make_float2(0.f, 0.f);
        if (gr < Nn) {
            acc = *reinterpret_cast<const float2*>(hin + (size_t)gr * Hh + 2 * lane); // self
            int e = __ldg(g_indptr + gr);
            int end = __ldg(g_indptr + gr + 1);
            for (; e + 4 <= end; e += 4) {
                int s0 = __ldg(g_idx + e);
                int s1 = __ldg(g_idx + e + 1);
                int s2 = __ldg(g_idx + e + 2);
                int s3 = __ldg(g_idx + e + 3);
                float2 v0 = *reinterpret_cast<const float2*>(hin + (size_t)s0 * Hh + 2 * lane);
                float2 v1 = *reinterpret_cast<const float2*>(hin + (size_t)s1 * Hh + 2 * lane);
                float2 v2 = *reinterpret_cast<const float2*>(hin + (size_t)s2 * Hh + 2 * lane);
                float2 v3 = *reinterpret_cast<const float2*>(hin + (size_t)s3 * Hh + 2 * lane);
                acc.x += v0.x + v1.x + v2.x + v3.x;
                acc.y += v0.y + v1.y + v2.y + v3.y;
            }
            for (; e < end; e++) {
                int s = __ldg(g_idx + e);
                float2 v = *reinterpret_cast<const float2*>(hin + (size_t)s * Hh + 2 * lane);
                acc.x += v.x; acc.y += v.y;
            }
        }
        *reinterpret_cast<float2*>(&sZ[r][2 * lane]) = acc;
    }
    {
        const float* Wg = g_W1 + layer * Hh * Hh;
        for (int i = tid * 4; i < 4096; i += 1024)
            *reinterpret_cast<float4*>(sW + i) = *reinterpret_cast<const float4*>(Wg + i);
    }
    __syncthreads();

    int tx = tid & 15;
    int ty = tid >> 4;

    float acc[4][4];
    #pragma unroll
    for (int i = 0; i < 4; i++)
        #pragma unroll
        for (int j = 0; j < 4; j++) acc[i][j] = 0.f;

    // GEMM1
    #pragma unroll
    for (int k0 = 0; k0 < 64; k0 += 4) {
        float za[4][4];
        #pragma unroll
        for (int i = 0; i < 4; i++) {
            float4 z4 = *reinterpret_cast<const float4*>(&sZ[ty * 4 + i][k0]);
            za[i][0] = z4.x; za[i][1] = z4.y; za[i][2] = z4.z; za[i][3] = z4.w;
        }
        #pragma unroll
        for (int kk = 0; kk < 4; kk++) {
            float4 w = *reinterpret_cast<const float4*>(sW + (k0 + kk) * 64 + tx * 4);
            #pragma unroll
            for (int i = 0; i < 4; i++) {
                acc[i][0] = fmaf(za[i][kk], w.x, acc[i][0]);
                acc[i][1] = fmaf(za[i][kk], w.y, acc[i][1]);
                acc[i][2] = fmaf(za[i][kk], w.z, acc[i][2]);
                acc[i][3] = fmaf(za[i][kk], w.w, acc[i][3]);
            }
        }
    }
    float4 c1v = *reinterpret_cast<const float4*>(g_c1 + layer * Hh + tx * 4);
    __syncthreads();

    #pragma unroll
    for (int i = 0; i < 4; i++) {
        float4 y;
        y.x = fmaxf(acc[i][0] + c1v.x, 0.f);
        y.y = fmaxf(acc[i][1] + c1v.y, 0.f);
        y.z = fmaxf(acc[i][2] + c1v.z, 0.f);
        y.w = fmaxf(acc[i][3] + c1v.w, 0.f);
        *reinterpret_cast<float4*>(&sZ[ty * 4 + i][tx * 4]) = y;
    }
    {
        const float* Wg = g_W2 + layer * Hh * Hh;
        for (int i = tid * 4; i < 4096; i += 1024)
            *reinterpret_cast<float4*>(sW + i) = *reinterpret_cast<const float4*>(Wg + i);
    }
    __syncthreads();

    #pragma unroll
    for (int i = 0; i < 4; i++)
        #pragma unroll
        for (int j = 0; j < 4; j++) acc[i][j] = 0.f;

    // GEMM2
    #pragma unroll
    for (int k0 = 0; k0 < 64; k0 += 4) {
        float za[4][4];
        #pragma unroll
        for (int i = 0; i < 4; i++) {
            float4 z4 = *reinterpret_cast<const float4*>(&sZ[ty * 4 + i][k0]);
            za[i][0] = z4.x; za[i][1] = z4.y; za[i][2] = z4.z; za[i][3] = z4.w;
        }
        #pragma unroll
        for (int kk = 0; kk < 4; kk++) {
            float4 w = *reinterpret_cast<const float4*>(sW + (k0 + kk) * 64 + tx * 4);
            #pragma unroll
            for (int i = 0; i < 4; i++) {
                acc[i][0] = fmaf(za[i][kk], w.x, acc[i][0]);
                acc[i][1] = fmaf(za[i][kk], w.y, acc[i][1]);
                acc[i][2] = fmaf(za[i][kk], w.z, acc[i][2]);
                acc[i][3] = fmaf(za[i][kk], w.w, acc[i][3]);
            }
        }
    }
    float4 c2v = *reinterpret_cast<const float4*>(g_c2 + layer * Hh + tx * 4);
    #pragma unroll
    for (int i = 0; i < 4; i++) {
        int gr = row0 + ty * 4 + i;
        if (gr < Nn) {
            float4 y;
            y.x = fmaxf(acc[i][0] + c2v.x, 0.f);
            y.y = fmaxf(acc[i][1] + c2v.y, 0.f);
            y.z = fmaxf(acc[i][2] + c2v.z, 0.f);
            y.w = fmaxf(acc[i][3] + c2v.w, 0.f);
            if (write_h)
                *reinterpret_cast<float4*>(hout + (size_t)gr * Hh + tx * 4) = y;
            int b = __ldg(batch + gr);
            float* pp = g_pool + (size_t)b * (Ll * Hh) + layer * Hh + tx * 4;
            asm volatile("red.global.add.v4.f32 [%0], {%1,%2,%3,%4};"
                         :: "l"(pp), "f"(y.x), "f"(y.y), "f"(y.z), "f"(y.w) : "memory");
        }
    }
}

// ---------------- head ----------------
__global__ void final_k(const float* __restrict__ W1, const float* __restrict__ b1,
                        const float* __restrict__ W2, const float* __restrict__ b2,
                        float* __restrict__ out) {
    int g = blockIdx.x;
    int j = threadIdx.x;   // 64 threads
    __shared__ float sp[Ll * Hh];
    __shared__ float sh[Hh];
    for (int i = j; i < Ll * Hh; i += 64) sp[i] = g_pool[(size_t)g * (Ll * Hh) + i];
    __syncthreads();
    float a = b1[j];
    #pragma unroll 8
    for (int k = 0; k < Ll * Hh; k++) a = fmaf(sp[k], W1[k * Hh + j], a);
    sh[j] = fmaxf(a, 0.f);
    __syncthreads();
    if (j < Cc) {
        float o = b2[j];
        #pragma unroll
        for (int k = 0; k < Hh; k++) o = fmaf(sh[k], W2[k * Cc + j], o);
        out[g * Cc + j] = o;
    }
}

// ---------------- launch ----------------
extern "C" void kernel_launch(void* const* d_in, const int* in_sizes, int n_in,
                              void* d_out, int out_size) {
    const float* x     = (const float*)d_in[0];
    const int*   ei    = (const int*)d_in[1];
    const int*   batch = (const int*)d_in[2];
    const float* cW1 = (const float*)d_in[3];
    const float* cb1 = (const float*)d_in[4];
    const float* g1  = (const float*)d_in[5];
    const float* be1 = (const float*)d_in[6];
    const float* m1  = (const float*)d_in[7];
    const float* v1  = (const float*)d_in[8];
    const float* cW2 = (const float*)d_in[9];
    const float* cb2 = (const float*)d_in[10];
    const float* g2  = (const float*)d_in[11];
    const float* be2 = (const float*)d_in[12];
    const float* m2  = (const float*)d_in[13];
    const float* v2  = (const float*)d_in[14];
    const float* l1W = (const float*)d_in[15];
    const float* l1b = (const float*)d_in[16];
    const float* l2W = (const float*)d_in[17];
    const float* l2b = (const float*)d_in[18];
    float* out = (float*)d_out;

    zero_k<<<(Nn + 256) / 256, 256>>>();
    fold_k<<<(Ll * Hh * Hh + 255) / 256, 256>>>(cW1, cb1, g1, be1, m1, v1,
                                                cW2, cb2, g2, be2, m2, v2);
    hist_k<<<(Ee + 255) / 256, 256>>>(ei);
    scanA_k<<<NCHUNK, 1024>>>();
    scanB_k<<<1, 64>>>();
    scanC_k<<<NCHUNK, 1024>>>();
    fill_k<<<(Ee + 255) / 256, 256>>>(ei);

    float* hbase;
    cudaGetSymbolAddress((void**)&hbase, g_h);

    const float* hin = x;
    for (int l = 0; l < Ll; l++) {
        float* hout = hbase + (size_t)l * Nn * Hh;
        mlp_k<<<(Nn + 63) / 64, 256>>>(hin, hout, batch, l, l < Ll - 1 ? 1 : 0);
        hin = hout;
    }
    final_k<<<Gg, 64>>>(l1W, l1b, l2W, l2b, out);
}

// round 7
// speedup vs baseline: 1.3129x; 1.0030x over previous
#include <cuda_runtime.h>

#define Nn 50000
#define Ee 800000
#define Hh 64
#define Ll 4
#define Gg 500
#define Cc 10
#define BN_EPS 1e-5f
#define NCHUNK 49   // ceil((Nn+1)/1024)

typedef unsigned long long u64;

__device__ __forceinline__ u64 pack2(float v) {
    u64 r;
    asm("mov.b64 %0, {%1, %1};" : "=l"(r) : "f"(v));
    return r;
}
__device__ __forceinline__ void fma2(u64 &d, u64 a, u64 b) {
    asm("fma.rn.f32x2 %0, %1, %2, %0;" : "+l"(d) : "l"(a), "l"(b));
}
__device__ __forceinline__ float2 unpack2(u64 v) {
    float2 r;
    asm("mov.b64 {%0, %1}, %2;" : "=f"(r.x), "=f"(r.y) : "l"(v));
    return r;
}

// ---------------- device scratch (static, 16B-aligned) ----------------
__device__ __align__(16) float g_h[(size_t)Ll * Nn * Hh]; // per-layer outputs (gather source)
__device__ __align__(16) float g_W1[Ll * Hh * Hh];
__device__ __align__(16) float g_W2[Ll * Hh * Hh];
__device__ __align__(16) float g_c1[Ll * Hh];
__device__ __align__(16) float g_c2[Ll * Hh];
__device__ __align__(16) float g_pool[Gg * Ll * Hh];
// CSR by destination
__device__ int g_cnt[Nn + 1];
__device__ int g_indptr[Nn + 1];
__device__ int g_cursor[Nn];
__device__ int g_idx[Ee];
__device__ int g_bsum[NCHUNK];
__device__ int g_boff[NCHUNK];

// ---------------- zero pool + counts ----------------
__global__ void zero_k() {
    int t = blockIdx.x * blockDim.x + threadIdx.x;
    const int tot_pool = Gg * Ll * Hh / 4;
    if (t < tot_pool)
        reinterpret_cast<float4*>(g_pool)[t] = make_float4(0.f, 0.f, 0.f, 0.f);
    if (t < Nn + 1) g_cnt[t] = 0;
}

// ---------------- fold BN into weights/bias ----------------
__global__ void fold_k(const float* __restrict__ W1, const float* __restrict__ b1,
                       const float* __restrict__ g1, const float* __restrict__ be1,
                       const float* __restrict__ m1, const float* __restrict__ v1,
                       const float* __restrict__ W2, const float* __restrict__ b2,
                       const float* __restrict__ g2, const float* __restrict__ be2,
                       const float* __restrict__ m2, const float* __restrict__ v2) {
    int idx = blockIdx.x * blockDim.x + threadIdx.x;
    if (idx >= Ll * Hh * Hh) return;
    int j = idx & (Hh - 1);
    int lk = idx >> 6;
    int l = lk >> 6;
    int k = lk & 63;
    int lj = l * Hh + j;
    float s1 = g1[lj] * rsqrtf(v1[lj] + BN_EPS);
    float s2 = g2[lj] * rsqrtf(v2[lj] + BN_EPS);
    g_W1[idx] = W1[idx] * s1;
    g_W2[idx] = W2[idx] * s2;
    if (k == 0) {
        g_c1[lj] = b1[lj] * s1 + be1[lj] - m1[lj] * s1;
        g_c2[lj] = b2[lj] * s2 + be2[lj] - m2[lj] * s2;
    }
}

// ---------------- CSR build ----------------
__global__ void hist_k(const int* __restrict__ ei) {
    int e = blockIdx.x * blockDim.x + threadIdx.x;
    if (e < Ee) atomicAdd(g_cnt + __ldg(ei + Ee + e), 1);
}

__global__ void scanA_k() {
    __shared__ int wsum[32];
    int t = threadIdx.x;
    int idx = blockIdx.x * 1024 + t;
    int v = (idx < Nn + 1) ? g_cnt[idx] : 0;
    #pragma unroll
    for (int off = 16; off > 0; off >>= 1)
        v += __shfl_down_sync(0xffffffffu, v, off);
    if ((t & 31) == 0) wsum[t >> 5] = v;
    __syncthreads();
    if (t < 32) {
        int s = wsum[t];
        #pragma unroll
        for (int off = 16; off > 0; off >>= 1)
            s += __shfl_down_sync(0xffffffffu, s, off);
        if (t == 0) g_bsum[blockIdx.x] = s;
    }
}

__global__ void scanB_k() {
    int t = threadIdx.x;  // 64 threads
    int v = (t < NCHUNK) ? g_bsum[t] : 0;
    __shared__ int s[64];
    s[t] = v;
    __syncthreads();
    for (int off = 1; off < 64; off <<= 1) {
        int a = (t >= off) ? s[t - off] : 0;
        __syncthreads();
        s[t] += a;
        __syncthreads();
    }
    if (t < NCHUNK) g_boff[t] = (t == 0) ? 0 : s[t - 1];
}

__global__ void scanC_k() {
    __shared__ int wsum[32];
    int t = threadIdx.x;
    int lane = t & 31;
    int wid = t >> 5;
    int idx = blockIdx.x * 1024 + t;
    int v = (idx < Nn + 1) ? g_cnt[idx] : 0;
    int incl = v;
    #pragma unroll
    for (int off = 1; off < 32; off <<= 1) {
        int n = __shfl_up_sync(0xffffffffu, incl, off);
        if (lane >= off) incl += n;
    }
    if (lane == 31) wsum[wid] = incl;
    __syncthreads();
    if (t < 32) {
        int s = wsum[t];
        #pragma unroll
        for (int off = 1; off < 32; off <<= 1) {
            int n = __shfl_up_sync(0xffffffffu, s, off);
            if (t >= off) s += n;
        }
        wsum[t] = s;
    }
    __syncthreads();
    int excl = incl - v + (wid > 0 ? wsum[wid - 1] : 0) + g_boff[blockIdx.x];
    if (idx < Nn + 1) {
        g_indptr[idx] = excl;
        if (idx < Nn) g_cursor[idx] = excl;
    }
}

__global__ void fill_k(const int* __restrict__ ei) {
    int e = blockIdx.x * blockDim.x + threadIdx.x;
    if (e >= Ee) return;
    int s = __ldg(ei + e);
    int d = __ldg(ei + Ee + e);
    int pos = atomicAdd(g_cursor + d, 1);
    g_idx[pos] = s;
}

// ---------------- fused gather + GIN MLP (f32x2 packed) + pool-red ----------------
__global__ void __launch_bounds__(256, 5) mlp_k(const float* __restrict__ hin,
                                                float* __restrict__ hout,
                                                const int* __restrict__ batch,
                                                int layer, int write_h) {
    __shared__ __align__(16) float sZ[64][68];
    __shared__ __align__(16) float sW[64 * 64];

    int tid = threadIdx.x;
    int row0 = blockIdx.x * 64;
    int wid = tid >> 5;
    int lane = tid & 31;

    // ---- gather phase: warp per 8 rows, lane owns 2 cols ----
    for (int rr = 0; rr < 8; rr++) {
        int r = wid * 8 + rr;
        int gr = row0 + r;
        float2 acc = make_float2(0.f, 0.f);
        if (gr < Nn) {
            acc = *reinterpret_cast<const float2*>(hin + (size_t)gr * Hh + 2 * lane); // self
            int e = __ldg(g_indptr + gr);
            int end = __ldg(g_indptr + gr + 1);
            for (; e + 4 <= end; e += 4) {
                int s0 = __ldg(g_idx + e);
                int s1 = __ldg(g_idx + e + 1);
                int s2 = __ldg(g_idx + e + 2);
                int s3 = __ldg(g_idx + e + 3);
                float2 v0 = *reinterpret_cast<const float2*>(hin + (size_t)s0 * Hh + 2 * lane);
                float2 v1 = *reinterpret_cast<const float2*>(hin + (size_t)s1 * Hh + 2 * lane);
                float2 v2 = *reinterpret_cast<const float2*>(hin + (size_t)s2 * Hh + 2 * lane);
                float2 v3 = *reinterpret_cast<const float2*>(hin + (size_t)s3 * Hh + 2 * lane);
                acc.x += v0.x + v1.x + v2.x + v3.x;
                acc.y += v0.y + v1.y + v2.y + v3.y;
            }
            for (; e < end; e++) {
                int s = __ldg(g_idx + e);
                float2 v = *reinterpret_cast<const float2*>(hin + (size_t)s * Hh + 2 * lane);
                acc.x += v.x; acc.y += v.y;
            }
        }
        *reinterpret_cast<float2*>(&sZ[r][2 * lane]) = acc;
    }
    {
        const float* Wg = g_W1 + layer * Hh * Hh;
        for (int i = tid * 4; i < 4096; i += 1024)
            *reinterpret_cast<float4*>(sW + i) = *reinterpret_cast<const float4*>(Wg + i);
    }
    __syncthreads();

    int tx = tid & 15;
    int ty = tid >> 4;

    u64 acc2[4][2];   // [row][col-pair], f32x2 accumulators (cols tx*4+0/1 and +2/3)
    #pragma unroll
    for (int i = 0; i < 4; i++) { acc2[i][0] = 0ull; acc2[i][1] = 0ull; }

    // GEMM1 (packed f32x2: W pairs straight from smem, z broadcast-packed)
    #pragma unroll
    for (int k0 = 0; k0 < 64; k0 += 4) {
        float4 z4[4];
        #pragma unroll
        for (int i = 0; i < 4; i++)
            z4[i] = *reinterpret_cast<const float4*>(&sZ[ty * 4 + i][k0]);
        #pragma unroll
        for (int kk = 0; kk < 4; kk++) {
            ulonglong2 w2 = *reinterpret_cast<const ulonglong2*>(sW + (k0 + kk) * 64 + tx * 4);
            #pragma unroll
            for (int i = 0; i < 4; i++) {
                float zv = (kk == 0) ? z4[i].x : (kk == 1) ? z4[i].y : (kk == 2) ? z4[i].z : z4[i].w;
                u64 zp = pack2(zv);
                fma2(acc2[i][0], zp, w2.x);
                fma2(acc2[i][1], zp, w2.y);
            }
        }
    }
    float4 c1v = *reinterpret_cast<const float4*>(g_c1 + layer * Hh + tx * 4);
    __syncthreads();

    // y1 = relu(acc + c1) -> sZ; reload sW with W2'
    #pragma unroll
    for (int i = 0; i < 4; i++) {
        float2 a01 = unpack2(acc2[i][0]);
        float2 a23 = unpack2(acc2[i][1]);
        float4 y;
        y.x = fmaxf(a01.x + c1v.x, 0.f);
        y.y = fmaxf(a01.y + c1v.y, 0.f);
        y.z = fmaxf(a23.x + c1v.z, 0.f);
        y.w = fmaxf(a23.y + c1v.w, 0.f);
        *reinterpret_cast<float4*>(&sZ[ty * 4 + i][tx * 4]) = y;
    }
    {
        const float* Wg = g_W2 + layer * Hh * Hh;
        for (int i = tid * 4; i < 4096; i += 1024)
            *reinterpret_cast<float4*>(sW + i) = *reinterpret_cast<const float4*>(Wg + i);
    }
    __syncthreads();

    #pragma unroll
    for (int i = 0; i < 4; i++) { acc2[i][0] = 0ull; acc2[i][1] = 0ull; }

    // GEMM2
    #pragma unroll
    for (int k0 = 0; k0 < 64; k0 += 4) {
        float4 z4[4];
        #pragma unroll
        for (int i = 0; i < 4; i++)
            z4[i] = *reinterpret_cast<const float4*>(&sZ[ty * 4 + i][k0]);
        #pragma unroll
        for (int kk = 0; kk < 4; kk++) {
            ulonglong2 w2 = *reinterpret_cast<const ulonglong2*>(sW + (k0 + kk) * 64 + tx * 4);
            #pragma unroll
            for (int i = 0; i < 4; i++) {
                float zv = (kk == 0) ? z4[i].x : (kk == 1) ? z4[i].y : (kk == 2) ? z4[i].z : z4[i].w;
                u64 zp = pack2(zv);
                fma2(acc2[i][0], zp, w2.x);
                fma2(acc2[i][1], zp, w2.y);
            }
        }
    }
    float4 c2v = *reinterpret_cast<const float4*>(g_c2 + layer * Hh + tx * 4);
    #pragma unroll
    for (int i = 0; i < 4; i++) {
        int gr = row0 + ty * 4 + i;
        if (gr < Nn) {
            float2 a01 = unpack2(acc2[i][0]);
            float2 a23 = unpack2(acc2[i][1]);
            float4 y;
            y.x = fmaxf(a01.x + c2v.x, 0.f);
            y.y = fmaxf(a01.y + c2v.y, 0.f);
            y.z = fmaxf(a23.x + c2v.z, 0.f);
            y.w = fmaxf(a23.y + c2v.w, 0.f);
            if (write_h)
                *reinterpret_cast<float4*>(hout + (size_t)gr * Hh + tx * 4) = y;
            int b = __ldg(batch + gr);
            float* pp = g_pool + (size_t)b * (Ll * Hh) + layer * Hh + tx * 4;
            asm volatile("red.global.add.v4.f32 [%0], {%1,%2,%3,%4};"
                         :: "l"(pp), "f"(y.x), "f"(y.y), "f"(y.z), "f"(y.w) : "memory");
        }
    }
}

// ---------------- head ----------------
__global__ void final_k(const float* __restrict__ W1, const float* __restrict__ b1,
                        const float* __restrict__ W2, const float* __restrict__ b2,
                        float* __restrict__ out) {
    int g = blockIdx.x;
    int j = threadIdx.x;   // 64 threads
    __shared__ float sp[Ll * Hh];
    __shared__ float sh[Hh];
    for (int i = j; i < Ll * Hh; i += 64) sp[i] = g_pool[(size_t)g * (Ll * Hh) + i];
    __syncthreads();
    float a = b1[j];
    #pragma unroll 8
    for (int k = 0; k < Ll * Hh; k++) a = fmaf(sp[k], W1[k * Hh + j], a);
    sh[j] = fmaxf(a, 0.f);
    __syncthreads();
    if (j < Cc) {
        float o = b2[j];
        #pragma unroll
        for (int k = 0; k < Hh; k++) o = fmaf(sh[k], W2[k * Cc + j], o);
        out[g * Cc + j] = o;
    }
}

// ---------------- launch ----------------
extern "C" void kernel_launch(void* const* d_in, const int* in_sizes, int n_in,
                              void* d_out, int out_size) {
    const float* x     = (const float*)d_in[0];
    const int*   ei    = (const int*)d_in[1];
    const int*   batch = (const int*)d_in[2];
    const float* cW1 = (const float*)d_in[3];
    const float* cb1 = (const float*)d_in[4];
    const float* g1  = (const float*)d_in[5];
    const float* be1 = (const float*)d_in[6];
    const float* m1  = (const float*)d_in[7];
    const float* v1  = (const float*)d_in[8];
    const float* cW2 = (const float*)d_in[9];
    const float* cb2 = (const float*)d_in[10];
    const float* g2  = (const float*)d_in[11];
    const float* be2 = (const float*)d_in[12];
    const float* m2  = (const float*)d_in[13];
    const float* v2  = (const float*)d_in[14];
    const float* l1W = (const float*)d_in[15];
    const float* l1b = (const float*)d_in[16];
    const float* l2W = (const float*)d_in[17];
    const float* l2b = (const float*)d_in[18];
    float* out = (float*)d_out;

    zero_k<<<(Nn + 256) / 256, 256>>>();
    fold_k<<<(Ll * Hh * Hh + 255) / 256, 256>>>(cW1, cb1, g1, be1, m1, v1,
                                                cW2, cb2, g2, be2, m2, v2);
    hist_k<<<(Ee + 255) / 256, 256>>>(ei);
    scanA_k<<<NCHUNK, 1024>>>();
    scanB_k<<<1, 64>>>();
    scanC_k<<<NCHUNK, 1024>>>();
    fill_k<<<(Ee + 255) / 256, 256>>>(ei);

    float* hbase;
    cudaGetSymbolAddress((void**)&hbase, g_h);

    const float* hin = x;
    for (int l = 0; l < Ll; l++) {
        float* hout = hbase + (size_t)l * Nn * Hh;
        mlp_k<<<(Nn + 63) / 64, 256>>>(hin, hout, batch, l, l < Ll - 1 ? 1 : 0);
        hin = hout;
    }
    final_k<<<Gg, 64>>>(l1W, l1b, l2W, l2b, out);
}

// round 8
// speedup vs baseline: 1.3303x; 1.0133x over previous
#include <cuda_runtime.h>

#define Nn 50000
#define Ee 800000
#define Hh 64
#define Ll 4
#define Gg 500
#define Cc 10
#define BN_EPS 1e-5f
#define NCHUNK 49   // ceil((Nn+1)/1024)

typedef unsigned long long u64;

__device__ __forceinline__ u64 pack2(float v) {
    u64 r;
    asm("mov.b64 %0, {%1, %1};" : "=l"(r) : "f"(v));
    return r;
}
__device__ __forceinline__ void fma2(u64 &d, u64 a, u64 b) {
    asm("fma.rn.f32x2 %0, %1, %2, %0;" : "+l"(d) : "l"(a), "l"(b));
}
__device__ __forceinline__ float2 unpack2(u64 v) {
    float2 r;
    asm("mov.b64 {%0, %1}, %2;" : "=f"(r.x), "=f"(r.y) : "l"(v));
    return r;
}

// ---------------- device scratch (zero-initialized at load; each replay restores zeros) ----
__device__ __align__(16) float g_h[(size_t)Ll * Nn * Hh];
__device__ __align__(16) float g_W1[Ll * Hh * Hh];
__device__ __align__(16) float g_W2[Ll * Hh * Hh];
__device__ __align__(16) float g_c1[Ll * Hh];
__device__ __align__(16) float g_c2[Ll * Hh];
__device__ __align__(16) float g_pool[Gg * Ll * Hh];   // zeroed by final_k after use
// CSR by destination
__device__ int g_cnt[Nn + 1];       // zeroed by fill_k after use
__device__ int g_indptr[Nn + 1];
__device__ int g_cursor[Nn];
__device__ int g_idx[Ee];
__device__ int g_bsum[NCHUNK];
__device__ int g_ready[NCHUNK];     // zeroed by fill_k after use

// ---------------- hist (edge->dst counts) + BN fold, fused ----------------
__global__ void histfold_k(const int* __restrict__ ei,
                           const float* __restrict__ W1, const float* __restrict__ b1,
                           const float* __restrict__ g1, const float* __restrict__ be1,
                           const float* __restrict__ m1, const float* __restrict__ v1,
                           const float* __restrict__ W2, const float* __restrict__ b2,
                           const float* __restrict__ g2, const float* __restrict__ be2,
                           const float* __restrict__ m2, const float* __restrict__ v2) {
    int t = blockIdx.x * blockDim.x + threadIdx.x;
    if (t < Ll * Hh * Hh) {
        int j = t & (Hh - 1);
        int lk = t >> 6;
        int l = lk >> 6;
        int k = lk & 63;
        int lj = l * Hh + j;
        float s1 = g1[lj] * rsqrtf(v1[lj] + BN_EPS);
        float s2 = g2[lj] * rsqrtf(v2[lj] + BN_EPS);
        g_W1[t] = W1[t] * s1;
        g_W2[t] = W2[t] * s2;
        if (k == 0) {
            g_c1[lj] = b1[lj] * s1 + be1[lj] - m1[lj] * s1;
            g_c2[lj] = b2[lj] * s2 + be2[lj] - m2[lj] * s2;
        }
    }
    if (t < Ee) atomicAdd(g_cnt + __ldg(ei + Ee + t), 1);
}

// ---------------- single-kernel scan (decoupled lookback; 49 blocks all resident) --------
__global__ void scan_k() {
    __shared__ int wsum[32];
    __shared__ int chunk_off;
    int b = blockIdx.x;
    int t = threadIdx.x;
    int lane = t & 31;
    int wid = t >> 5;
    int idx = b * 1024 + t;
    int v = (idx < Nn + 1) ? g_cnt[idx] : 0;

    // warp inclusive scan
    int incl = v;
    #pragma unroll
    for (int off = 1; off < 32; off <<= 1) {
        int n = __shfl_up_sync(0xffffffffu, incl, off);
        if (lane >= off) incl += n;
    }
    if (lane == 31) wsum[wid] = incl;
    __syncthreads();
    if (t < 32) {
        int s = wsum[t];
        #pragma unroll
        for (int off = 1; off < 32; off <<= 1) {
            int n = __shfl_up_sync(0xffffffffu, s, off);
            if (t >= off) s += n;
        }
        wsum[t] = s;   // inclusive warp-sum scan; wsum[31] = block total
    }
    __syncthreads();

    // publish block total, then gather predecessor offsets (lookback)
    if (t == 0) {
        g_bsum[b] = wsum[31];
        __threadfence();
        atomicExch(g_ready + b, 1);
    }
    if (t < b) {                 // at most 48 waiting lanes (warps 0-1)
        while (atomicAdd(g_ready + t, 0) == 0) {}
    }
    __syncthreads();
    if (t == 0) {
        int off = 0;
        for (int i = 0; i < b; i++) off += g_bsum[i];
        chunk_off = off;
    }
    __syncthreads();

    int excl = incl - v + (wid > 0 ? wsum[wid - 1] : 0) + chunk_off;
    if (idx < Nn + 1) {
        g_indptr[idx] = excl;
        if (idx < Nn) g_cursor[idx] = excl;
    }
}

// ---------------- fill CSR + restore zeros for next replay ----------------
__global__ void fill_k(const int* __restrict__ ei) {
    int e = blockIdx.x * blockDim.x + threadIdx.x;
    if (e < Nn + 1) g_cnt[e] = 0;          // consumed by scan_k; reset for next call
    if (e < NCHUNK) g_ready[e] = 0;        // reset lookback flags
    if (e >= Ee) return;
    int s = __ldg(ei + e);
    int d = __ldg(ei + Ee + e);
    int pos = atomicAdd(g_cursor + d, 1);
    g_idx[pos] = s;
}

// ---------------- fused gather + GIN MLP (f32x2 packed) + pool-red ----------------
__global__ void __launch_bounds__(256, 5) mlp_k(const float* __restrict__ hin,
                                                float* __restrict__ hout,
                                                const int* __restrict__ batch,
                                                int layer, int write_h) {
    __shared__ __align__(16) float sZ[64][68];
    __shared__ __align__(16) float sW[64 * 64];

    int tid = threadIdx.x;
    int row0 = blockIdx.x * 64;
    int wid = tid >> 5;
    int lane = tid & 31;

    // ---- gather phase: warp per 8 rows, lane owns 2 cols ----
    for (int rr = 0; rr < 8; rr++) {
        int r = wid * 8 + rr;
        int gr = row0 + r;
        float2 acc = make_float2(0.f, 0.f);
        if (gr < Nn) {
            acc = *reinterpret_cast<const float2*>(hin + (size_t)gr * Hh + 2 * lane); // self
            int e = __ldg(g_indptr + gr);
            int end = __ldg(g_indptr + gr + 1);
            for (; e + 4 <= end; e += 4) {
                int s0 = __ldg(g_idx + e);
                int s1 = __ldg(g_idx + e + 1);
                int s2 = __ldg(g_idx + e + 2);
                int s3 = __ldg(g_idx + e + 3);
                float2 v0 = *reinterpret_cast<const float2*>(hin + (size_t)s0 * Hh + 2 * lane);
                float2 v1 = *reinterpret_cast<const float2*>(hin + (size_t)s1 * Hh + 2 * lane);
                float2 v2 = *reinterpret_cast<const float2*>(hin + (size_t)s2 * Hh + 2 * lane);
                float2 v3 = *reinterpret_cast<const float2*>(hin + (size_t)s3 * Hh + 2 * lane);
                acc.x += v0.x + v1.x + v2.x + v3.x;
                acc.y += v0.y + v1.y + v2.y + v3.y;
            }
            for (; e < end; e++) {
                int s = __ldg(g_idx + e);
                float2 v = *reinterpret_cast<const float2*>(hin + (size_t)s * Hh + 2 * lane);
                acc.x += v.x; acc.y += v.y;
            }
        }
        *reinterpret_cast<float2*>(&sZ[r][2 * lane]) = acc;
    }
    {
        const float* Wg = g_W1 + layer * Hh * Hh;
        for (int i = tid * 4; i < 4096; i += 1024)
            *reinterpret_cast<float4*>(sW + i) = *reinterpret_cast<const float4*>(Wg + i);
    }
    __syncthreads();

    int tx = tid & 15;
    int ty = tid >> 4;

    u64 acc2[4][2];
    #pragma unroll
    for (int i = 0; i < 4; i++) { acc2[i][0] = 0ull; acc2[i][1] = 0ull; }

    // GEMM1
    #pragma unroll
    for (int k0 = 0; k0 < 64; k0 += 4) {
        float4 z4[4];
        #pragma unroll
        for (int i = 0; i < 4; i++)
            z4[i] = *reinterpret_cast<const float4*>(&sZ[ty * 4 + i][k0]);
        #pragma unroll
        for (int kk = 0; kk < 4; kk++) {
            ulonglong2 w2 = *reinterpret_cast<const ulonglong2*>(sW + (k0 + kk) * 64 + tx * 4);
            #pragma unroll
            for (int i = 0; i < 4; i++) {
                float zv = (kk == 0) ? z4[i].x : (kk == 1) ? z4[i].y : (kk == 2) ? z4[i].z : z4[i].w;
                u64 zp = pack2(zv);
                fma2(acc2[i][0], zp, w2.x);
                fma2(acc2[i][1], zp, w2.y);
            }
        }
    }
    float4 c1v = *reinterpret_cast<const float4*>(g_c1 + layer * Hh + tx * 4);
    __syncthreads();

    #pragma unroll
    for (int i = 0; i < 4; i++) {
        float2 a01 = unpack2(acc2[i][0]);
        float2 a23 = unpack2(acc2[i][1]);
        float4 y;
        y.x = fmaxf(a01.x + c1v.x, 0.f);
        y.y = fmaxf(a01.y + c1v.y, 0.f);
        y.z = fmaxf(a23.x + c1v.z, 0.f);
        y.w = fmaxf(a23.y + c1v.w, 0.f);
        *reinterpret_cast<float4*>(&sZ[ty * 4 + i][tx * 4]) = y;
    }
    {
        const float* Wg = g_W2 + layer * Hh * Hh;
        for (int i = tid * 4; i < 4096; i += 1024)
            *reinterpret_cast<float4*>(sW + i) = *reinterpret_cast<const float4*>(Wg + i);
    }
    __syncthreads();

    #pragma unroll
    for (int i = 0; i < 4; i++) { acc2[i][0] = 0ull; acc2[i][1] = 0ull; }

    // GEMM2
    #pragma unroll
    for (int k0 = 0; k0 < 64; k0 += 4) {
        float4 z4[4];
        #pragma unroll
        for (int i = 0; i < 4; i++)
            z4[i] = *reinterpret_cast<const float4*>(&sZ[ty * 4 + i][k0]);
        #pragma unroll
        for (int kk = 0; kk < 4; kk++) {
            ulonglong2 w2 = *reinterpret_cast<const ulonglong2*>(sW + (k0 + kk) * 64 + tx * 4);
            #pragma unroll
            for (int i = 0; i < 4; i++) {
                float zv = (kk == 0) ? z4[i].x : (kk == 1) ? z4[i].y : (kk == 2) ? z4[i].z : z4[i].w;
                u64 zp = pack2(zv);
                fma2(acc2[i][0], zp, w2.x);
                fma2(acc2[i][1], zp, w2.y);
            }
        }
    }
    float4 c2v = *reinterpret_cast<const float4*>(g_c2 + layer * Hh + tx * 4);
    #pragma unroll
    for (int i = 0; i < 4; i++) {
        int gr = row0 + ty * 4 + i;
        if (gr < Nn) {
            float2 a01 = unpack2(acc2[i][0]);
            float2 a23 = unpack2(acc2[i][1]);
            float4 y;
            y.x = fmaxf(a01.x + c2v.x, 0.f);
            y.y = fmaxf(a01.y + c2v.y, 0.f);
            y.z = fmaxf(a23.x + c2v.z, 0.f);
            y.w = fmaxf(a23.y + c2v.w, 0.f);
            if (write_h)
                *reinterpret_cast<float4*>(hout + (size_t)gr * Hh + tx * 4) = y;
            int b = __ldg(batch + gr);
            float* pp = g_pool + (size_t)b * (Ll * Hh) + layer * Hh + tx * 4;
            asm volatile("red.global.add.v4.f32 [%0], {%1,%2,%3,%4};"
                         :: "l"(pp), "f"(y.x), "f"(y.y), "f"(y.z), "f"(y.w) : "memory");
        }
    }
}

// ---------------- head (also re-zeroes g_pool for next replay) ----------------
__global__ void final_k(const float* __restrict__ W1, const float* __restrict__ b1,
                        const float* __restrict__ W2, const float* __restrict__ b2,
                        float* __restrict__ out) {
    int g = blockIdx.x;
    int j = threadIdx.x;   // 64 threads
    __shared__ float sp[Ll * Hh];
    __shared__ float sh[Hh];
    for (int i = j; i < Ll * Hh; i += 64) sp[i] = g_pool[(size_t)g * (Ll * Hh) + i];
    __syncthreads();
    // reset pool row for next replay (value already in smem)
    *reinterpret_cast<float4*>(g_pool + (size_t)g * (Ll * Hh) + j * 4) =
        make_float4(0.f, 0.f, 0.f, 0.f);
    float a = b1[j];
    #pragma unroll 8
    for (int k = 0; k < Ll * Hh; k++) a = fmaf(sp[k], W1[k * Hh + j], a);
    sh[j] = fmaxf(a, 0.f);
    __syncthreads();
    if (j < Cc) {
        float o = b2[j];
        #pragma unroll
        for (int k = 0; k < Hh; k++) o = fmaf(sh[k], W2[k * Cc + j], o);
        out[g * Cc + j] = o;
    }
}

// ---------------- launch (8 kernels; mlp layer 0 is launch #4 for ncu) ----------------
extern "C" void kernel_launch(void* const* d_in, const int* in_sizes, int n_in,
                              void* d_out, int out_size) {
    const float* x     = (const float*)d_in[0];
    const int*   ei    = (const int*)d_in[1];
    const int*   batch = (const int*)d_in[2];
    const float* cW1 = (const float*)d_in[3];
    const float* cb1 = (const float*)d_in[4];
    const float* g1  = (const float*)d_in[5];
    const float* be1 = (const float*)d_in[6];
    const float* m1  = (const float*)d_in[7];
    const float* v1  = (const float*)d_in[8];
    const float* cW2 = (const float*)d_in[9];
    const float* cb2 = (const float*)d_in[10];
    const float* g2  = (const float*)d_in[11];
    const float* be2 = (const float*)d_in[12];
    const float* m2  = (const float*)d_in[13];
    const float* v2  = (const float*)d_in[14];
    const float* l1W = (const float*)d_in[15];
    const float* l1b = (const float*)d_in[16];
    const float* l2W = (const float*)d_in[17];
    const float* l2b = (const float*)d_in[18];
    float* out = (float*)d_out;

    histfold_k<<<(Ee + 255) / 256, 256>>>(ei, cW1, cb1, g1, be1, m1, v1,
                                          cW2, cb2, g2, be2, m2, v2);
    scan_k<<<NCHUNK, 1024>>>();
    fill_k<<<(Ee + 255) / 256, 256>>>(ei);

    float* hbase;
    cudaGetSymbolAddress((void**)&hbase, g_h);

    const float* hin = x;
    for (int l = 0; l < Ll; l++) {
        float* hout = hbase + (size_t)l * Nn * Hh;
        mlp_k<<<(Nn + 63) / 64, 256>>>(hin, hout, batch, l, l < Ll - 1 ? 1 : 0);
        hin = hout;
    }
    final_k<<<Gg, 64>>>(l1W, l1b, l2W, l2b, out);
}

// round 9
// speedup vs baseline: 1.3832x; 1.0398x over previous
#include <cuda_runtime.h>

#define Nn 50000
#define Ee 800000
#define Hh 64
#define Ll 4
#define Gg 500
#define Cc 10
#define BN_EPS 1e-5f
#define NCHUNK 49   // ceil((Nn+1)/1024)

typedef unsigned long long u64;

__device__ __forceinline__ u64 pack2(float v) {
    u64 r;
    asm("mov.b64 %0, {%1, %1};" : "=l"(r) : "f"(v));
    return r;
}
__device__ __forceinline__ void fma2(u64 &d, u64 a, u64 b) {
    asm("fma.rn.f32x2 %0, %1, %2, %0;" : "+l"(d) : "l"(a), "l"(b));
}
__device__ __forceinline__ float2 unpack2(u64 v) {
    float2 r;
    asm("mov.b64 {%0, %1}, %2;" : "=f"(r.x), "=f"(r.y) : "l"(v));
    return r;
}

// ---------------- device scratch (zero-initialized at load; each replay restores zeros) ----
__device__ __align__(16) float g_h[(size_t)Ll * Nn * Hh];
__device__ __align__(16) float g_W1[Ll * Hh * Hh];
__device__ __align__(16) float g_W2[Ll * Hh * Hh];
__device__ __align__(16) float g_c1[Ll * Hh];
__device__ __align__(16) float g_c2[Ll * Hh];
__device__ __align__(16) float g_pool[Gg * Ll * Hh];   // zeroed by final_k after use
// CSR by destination
__device__ int g_cnt[Nn + 1];       // zeroed by fill_k after use
__device__ int g_indptr[Nn + 1];
__device__ int g_cursor[Nn];
__device__ int g_idx[Ee];
__device__ int g_bsum[NCHUNK];
__device__ int g_ready[NCHUNK];     // zeroed by fill_k after use

// ---------------- hist (edge->dst counts) + BN fold, fused ----------------
__global__ void histfold_k(const int* __restrict__ ei,
                           const float* __restrict__ W1, const float* __restrict__ b1,
                           const float* __restrict__ g1, const float* __restrict__ be1,
                           const float* __restrict__ m1, const float* __restrict__ v1,
                           const float* __restrict__ W2, const float* __restrict__ b2,
                           const float* __restrict__ g2, const float* __restrict__ be2,
                           const float* __restrict__ m2, const float* __restrict__ v2) {
    int t = blockIdx.x * blockDim.x + threadIdx.x;
    if (t < Ll * Hh * Hh) {
        int j = t & (Hh - 1);
        int lk = t >> 6;
        int l = lk >> 6;
        int k = lk & 63;
        int lj = l * Hh + j;
        float s1 = g1[lj] * rsqrtf(v1[lj] + BN_EPS);
        float s2 = g2[lj] * rsqrtf(v2[lj] + BN_EPS);
        g_W1[t] = W1[t] * s1;
        g_W2[t] = W2[t] * s2;
        if (k == 0) {
            g_c1[lj] = b1[lj] * s1 + be1[lj] - m1[lj] * s1;
            g_c2[lj] = b2[lj] * s2 + be2[lj] - m2[lj] * s2;
        }
    }
    if (t < Ee) atomicAdd(g_cnt + __ldg(ei + Ee + t), 1);
}

// ---------------- single-kernel scan (decoupled lookback; 49 blocks all resident) --------
__global__ void scan_k() {
    __shared__ int wsum[32];
    __shared__ int chunk_off;
    int b = blockIdx.x;
    int t = threadIdx.x;
    int lane = t & 31;
    int wid = t >> 5;
    int idx = b * 1024 + t;
    int v = (idx < Nn + 1) ? g_cnt[idx] : 0;

    int incl = v;
    #pragma unroll
    for (int off = 1; off < 32; off <<= 1) {
        int n = __shfl_up_sync(0xffffffffu, incl, off);
        if (lane >= off) incl += n;
    }
    if (lane == 31) wsum[wid] = incl;
    __syncthreads();
    if (t < 32) {
        int s = wsum[t];
        #pragma unroll
        for (int off = 1; off < 32; off <<= 1) {
            int n = __shfl_up_sync(0xffffffffu, s, off);
            if (t >= off) s += n;
        }
        wsum[t] = s;
    }
    __syncthreads();

    if (t == 0) {
        g_bsum[b] = wsum[31];
        __threadfence();
        atomicExch(g_ready + b, 1);
    }
    if (t < b) {
        while (atomicAdd(g_ready + t, 0) == 0) {}
    }
    __syncthreads();
    if (t == 0) {
        int off = 0;
        for (int i = 0; i < b; i++) off += g_bsum[i];
        chunk_off = off;
    }
    __syncthreads();

    int excl = incl - v + (wid > 0 ? wsum[wid - 1] : 0) + chunk_off;
    if (idx < Nn + 1) {
        g_indptr[idx] = excl;
        if (idx < Nn) g_cursor[idx] = excl;
    }
}

// ---------------- fill CSR + restore zeros for next replay ----------------
__global__ void fill_k(const int* __restrict__ ei) {
    int e = blockIdx.x * blockDim.x + threadIdx.x;
    if (e < Nn + 1) g_cnt[e] = 0;
    if (e < NCHUNK) g_ready[e] = 0;
    if (e >= Ee) return;
    int s = __ldg(ei + e);
    int d = __ldg(ei + Ee + e);
    int pos = atomicAdd(g_cursor + d, 1);
    g_idx[pos] = s;
}

// ---------------- fused gather + GIN MLP (f32x2 packed) + pool-red ----------------
// Gather: half-warp per row (lane owns float4 = 4 cols), two rows in flight per warp.
__global__ void __launch_bounds__(256, 5) mlp_k(const float* __restrict__ hin,
                                                float* __restrict__ hout,
                                                const int* __restrict__ batch,
                                                int layer, int write_h) {
    __shared__ __align__(16) float sZ[64][68];
    __shared__ __align__(16) float sW[64 * 64];

    int tid = threadIdx.x;
    int row0 = blockIdx.x * 64;
    int wid = tid >> 5;
    int lane = tid & 31;
    int hw = lane >> 4;     // half-warp id (0/1) -> which of the row pair
    int hl = lane & 15;     // lane within half-warp -> 4-col group

    // ---- gather phase: 4 row-pairs per warp, half-warp per row, float4 per lane ----
    for (int rp = 0; rp < 4; rp++) {
        int r = wid * 8 + rp * 2 + hw;
        int gr = row0 + r;
        float4 acc = make_float4(0.f, 0.f, 0.f, 0.f);
        if (gr < Nn) {
            acc = *reinterpret_cast<const float4*>(hin + (size_t)gr * Hh + 4 * hl); // self
            int e = __ldg(g_indptr + gr);
            int end = __ldg(g_indptr + gr + 1);
            for (; e + 4 <= end; e += 4) {
                int s0 = __ldg(g_idx + e);
                int s1 = __ldg(g_idx + e + 1);
                int s2 = __ldg(g_idx + e + 2);
                int s3 = __ldg(g_idx + e + 3);
                float4 v0 = *reinterpret_cast<const float4*>(hin + (size_t)s0 * Hh + 4 * hl);
                float4 v1 = *reinterpret_cast<const float4*>(hin + (size_t)s1 * Hh + 4 * hl);
                float4 v2 = *reinterpret_cast<const float4*>(hin + (size_t)s2 * Hh + 4 * hl);
                float4 v3 = *reinterpret_cast<const float4*>(hin + (size_t)s3 * Hh + 4 * hl);
                acc.x += v0.x + v1.x + v2.x + v3.x;
                acc.y += v0.y + v1.y + v2.y + v3.y;
                acc.z += v0.z + v1.z + v2.z + v3.z;
                acc.w += v0.w + v1.w + v2.w + v3.w;
            }
            for (; e < end; e++) {
                int s = __ldg(g_idx + e);
                float4 v = *reinterpret_cast<const float4*>(hin + (size_t)s * Hh + 4 * hl);
                acc.x += v.x; acc.y += v.y; acc.z += v.z; acc.w += v.w;
            }
        }
        *reinterpret_cast<float4*>(&sZ[r][4 * hl]) = acc;
    }
    {
        const float* Wg = g_W1 + layer * Hh * Hh;
        for (int i = tid * 4; i < 4096; i += 1024)
            *reinterpret_cast<float4*>(sW + i) = *reinterpret_cast<const float4*>(Wg + i);
    }
    __syncthreads();

    int tx = tid & 15;
    int ty = tid >> 4;

    u64 acc2[4][2];
    #pragma unroll
    for (int i = 0; i < 4; i++) { acc2[i][0] = 0ull; acc2[i][1] = 0ull; }

    // GEMM1
    #pragma unroll
    for (int k0 = 0; k0 < 64; k0 += 4) {
        float4 z4[4];
        #pragma unroll
        for (int i = 0; i < 4; i++)
            z4[i] = *reinterpret_cast<const float4*>(&sZ[ty * 4 + i][k0]);
        #pragma unroll
        for (int kk = 0; kk < 4; kk++) {
            ulonglong2 w2 = *reinterpret_cast<const ulonglong2*>(sW + (k0 + kk) * 64 + tx * 4);
            #pragma unroll
            for (int i = 0; i < 4; i++) {
                float zv = (kk == 0) ? z4[i].x : (kk == 1) ? z4[i].y : (kk == 2) ? z4[i].z : z4[i].w;
                u64 zp = pack2(zv);
                fma2(acc2[i][0], zp, w2.x);
                fma2(acc2[i][1], zp, w2.y);
            }
        }
    }
    float4 c1v = *reinterpret_cast<const float4*>(g_c1 + layer * Hh + tx * 4);
    __syncthreads();

    #pragma unroll
    for (int i = 0; i < 4; i++) {
        float2 a01 = unpack2(acc2[i][0]);
        float2 a23 = unpack2(acc2[i][1]);
        float4 y;
        y.x = fmaxf(a01.x + c1v.x, 0.f);
        y.y = fmaxf(a01.y + c1v.y, 0.f);
        y.z = fmaxf(a23.x + c1v.z, 0.f);
        y.w = fmaxf(a23.y + c1v.w, 0.f);
        *reinterpret_cast<float4*>(&sZ[ty * 4 + i][tx * 4]) = y;
    }
    {
        const float* Wg = g_W2 + layer * Hh * Hh;
        for (int i = tid * 4; i < 4096; i += 1024)
            *reinterpret_cast<float4*>(sW + i) = *reinterpret_cast<const float4*>(Wg + i);
    }
    __syncthreads();

    #pragma unroll
    for (int i = 0; i < 4; i++) { acc2[i][0] = 0ull; acc2[i][1] = 0ull; }

    // GEMM2
    #pragma unroll
    for (int k0 = 0; k0 < 64; k0 += 4) {
        float4 z4[4];
        #pragma unroll
        for (int i = 0; i < 4; i++)
            z4[i] = *reinterpret_cast<const float4*>(&sZ[ty * 4 + i][k0]);
        #pragma unroll
        for (int kk = 0; kk < 4; kk++) {
            ulonglong2 w2 = *reinterpret_cast<const ulonglong2*>(sW + (k0 + kk) * 64 + tx * 4);
            #pragma unroll
            for (int i = 0; i < 4; i++) {
                float zv = (kk == 0) ? z4[i].x : (kk == 1) ? z4[i].y : (kk == 2) ? z4[i].z : z4[i].w;
                u64 zp = pack2(zv);
                fma2(acc2[i][0], zp, w2.x);
                fma2(acc2[i][1], zp, w2.y);
            }
        }
    }
    float4 c2v = *reinterpret_cast<const float4*>(g_c2 + layer * Hh + tx * 4);
    #pragma unroll
    for (int i = 0; i < 4; i++) {
        int gr = row0 + ty * 4 + i;
        if (gr < Nn) {
            float2 a01 = unpack2(acc2[i][0]);
            float2 a23 = unpack2(acc2[i][1]);
            float4 y;
            y.x = fmaxf(a01.x + c2v.x, 0.f);
            y.y = fmaxf(a01.y + c2v.y, 0.f);
            y.z = fmaxf(a23.x + c2v.z, 0.f);
            y.w = fmaxf(a23.y + c2v.w, 0.f);
            if (write_h)
                *reinterpret_cast<float4*>(hout + (size_t)gr * Hh + tx * 4) = y;
            int b = __ldg(batch + gr);
            float* pp = g_pool + (size_t)b * (Ll * Hh) + layer * Hh + tx * 4;
            asm volatile("red.global.add.v4.f32 [%0], {%1,%2,%3,%4};"
                         :: "l"(pp), "f"(y.x), "f"(y.y), "f"(y.z), "f"(y.w) : "memory");
        }
    }
}

// ---------------- head (also re-zeroes g_pool for next replay) ----------------
__global__ void final_k(const float* __restrict__ W1, const float* __restrict__ b1,
                        const float* __restrict__ W2, const float* __restrict__ b2,
                        float* __restrict__ out) {
    int g = blockIdx.x;
    int j = threadIdx.x;   // 64 threads
    __shared__ float sp[Ll * Hh];
    __shared__ float sh[Hh];
    for (int i = j; i < Ll * Hh; i += 64) sp[i] = g_pool[(size_t)g * (Ll * Hh) + i];
    __syncthreads();
    *reinterpret_cast<float4*>(g_pool + (size_t)g * (Ll * Hh) + j * 4) =
        make_float4(0.f, 0.f, 0.f, 0.f);
    float a = b1[j];
    #pragma unroll 8
    for (int k = 0; k < Ll * Hh; k++) a = fmaf(sp[k], W1[k * Hh + j], a);
    sh[j] = fmaxf(a, 0.f);
    __syncthreads();
    if (j < Cc) {
        float o = b2[j];
        #pragma unroll
        for (int k = 0; k < Hh; k++) o = fmaf(sh[k], W2[k * Cc + j], o);
        out[g * Cc + j] = o;
    }
}

// ---------------- launch (8 kernels; mlp layer 0 is launch #4 for ncu) ----------------
extern "C" void kernel_launch(void* const* d_in, const int* in_sizes, int n_in,
                              void* d_out, int out_size) {
    const float* x     = (const float*)d_in[0];
    const int*   ei    = (const int*)d_in[1];
    const int*   batch = (const int*)d_in[2];
    const float* cW1 = (const float*)d_in[3];
    const float* cb1 = (const float*)d_in[4];
    const float* g1  = (const float*)d_in[5];
    const float* be1 = (const float*)d_in[6];
    const float* m1  = (const float*)d_in[7];
    const float* v1  = (const float*)d_in[8];
    const float* cW2 = (const float*)d_in[9];
    const float* cb2 = (const float*)d_in[10];
    const float* g2  = (const float*)d_in[11];
    const float* be2 = (const float*)d_in[12];
    const float* m2  = (const float*)d_in[13];
    const float* v2  = (const float*)d_in[14];
    const float* l1W = (const float*)d_in[15];
    const float* l1b = (const float*)d_in[16];
    const float* l2W = (const float*)d_in[17];
    const float* l2b = (const float*)d_in[18];
    float* out = (float*)d_out;

    histfold_k<<<(Ee + 255) / 256, 256>>>(ei, cW1, cb1, g1, be1, m1, v1,
                                          cW2, cb2, g2, be2, m2, v2);
    scan_k<<<NCHUNK, 1024>>>();
    fill_k<<<(Ee + 255) / 256, 256>>>(ei);

    float* hbase;
    cudaGetSymbolAddress((void**)&hbase, g_h);

    const float* hin = x;
    for (int l = 0; l < Ll; l++) {
        float* hout = hbase + (size_t)l * Nn * Hh;
        mlp_k<<<(Nn + 63) / 64, 256>>>(hin, hout, batch, l, l < Ll - 1 ? 1 : 0);
        hin = hout;
    }
    final_k<<<Gg, 64>>>(l1W, l1b, l2W, l2b, out);
}

// round 10
// speedup vs baseline: 1.4352x; 1.0376x over previous
#include <cuda_runtime.h>

#define Nn 50000
#define Ee 800000
#define Hh 64
#define Ll 4
#define Gg 500
#define Cc 10
#define BN_EPS 1e-5f
#define NCHUNK 49   // ceil((Nn+1)/1024)

typedef unsigned long long u64;

__device__ __forceinline__ u64 pack2(float v) {
    u64 r;
    asm("mov.b64 %0, {%1, %1};" : "=l"(r) : "f"(v));
    return r;
}
__device__ __forceinline__ void fma2(u64 &d, u64 a, u64 b) {
    asm("fma.rn.f32x2 %0, %1, %2, %0;" : "+l"(d) : "l"(a), "l"(b));
}
__device__ __forceinline__ float2 unpack2(u64 v) {
    float2 r;
    asm("mov.b64 {%0, %1}, %2;" : "=f"(r.x), "=f"(r.y) : "l"(v));
    return r;
}

// ---------------- device scratch ----------------
__device__ __align__(16) float g_h[(size_t)Ll * Nn * Hh];
__device__ __align__(16) float g_z[(size_t)Nn * Hh];      // gathered z = self + neighbor-sum
__device__ __align__(16) float g_W1[Ll * Hh * Hh];
__device__ __align__(16) float g_W2[Ll * Hh * Hh];
__device__ __align__(16) float g_c1[Ll * Hh];
__device__ __align__(16) float g_c2[Ll * Hh];
__device__ __align__(16) float g_pool[Gg * Ll * Hh];   // zeroed by final_k after use
// CSR by destination
__device__ int g_cnt[Nn + 1];       // zeroed by fill_k after use
__device__ int g_indptr[Nn + 1];
__device__ int g_cursor[Nn];
__device__ int g_idx[Ee];
__device__ int g_bsum[NCHUNK];
__device__ int g_ready[NCHUNK];     // zeroed by fill_k after use

// ---------------- hist (edge->dst counts) + BN fold, fused ----------------
__global__ void histfold_k(const int* __restrict__ ei,
                           const float* __restrict__ W1, const float* __restrict__ b1,
                           const float* __restrict__ g1, const float* __restrict__ be1,
                           const float* __restrict__ m1, const float* __restrict__ v1,
                           const float* __restrict__ W2, const float* __restrict__ b2,
                           const float* __restrict__ g2, const float* __restrict__ be2,
                           const float* __restrict__ m2, const float* __restrict__ v2) {
    int t = blockIdx.x * blockDim.x + threadIdx.x;
    if (t < Ll * Hh * Hh) {
        int j = t & (Hh - 1);
        int lk = t >> 6;
        int l = lk >> 6;
        int k = lk & 63;
        int lj = l * Hh + j;
        float s1 = g1[lj] * rsqrtf(v1[lj] + BN_EPS);
        float s2 = g2[lj] * rsqrtf(v2[lj] + BN_EPS);
        g_W1[t] = W1[t] * s1;
        g_W2[t] = W2[t] * s2;
        if (k == 0) {
            g_c1[lj] = b1[lj] * s1 + be1[lj] - m1[lj] * s1;
            g_c2[lj] = b2[lj] * s2 + be2[lj] - m2[lj] * s2;
        }
    }
    if (t < Ee) atomicAdd(g_cnt + __ldg(ei + Ee + t), 1);
}

// ---------------- single-kernel scan (decoupled lookback) ----------------
__global__ void scan_k() {
    __shared__ int wsum[32];
    __shared__ int chunk_off;
    int b = blockIdx.x;
    int t = threadIdx.x;
    int lane = t & 31;
    int wid = t >> 5;
    int idx = b * 1024 + t;
    int v = (idx < Nn + 1) ? g_cnt[idx] : 0;

    int incl = v;
    #pragma unroll
    for (int off = 1; off < 32; off <<= 1) {
        int n = __shfl_up_sync(0xffffffffu, incl, off);
        if (lane >= off) incl += n;
    }
    if (lane == 31) wsum[wid] = incl;
    __syncthreads();
    if (t < 32) {
        int s = wsum[t];
        #pragma unroll
        for (int off = 1; off < 32; off <<= 1) {
            int n = __shfl_up_sync(0xffffffffu, s, off);
            if (t >= off) s += n;
        }
        wsum[t] = s;
    }
    __syncthreads();

    if (t == 0) {
        g_bsum[b] = wsum[31];
        __threadfence();
        atomicExch(g_ready + b, 1);
    }
    if (t < b) {
        while (atomicAdd(g_ready + t, 0) == 0) {}
    }
    __syncthreads();
    if (t == 0) {
        int off = 0;
        for (int i = 0; i < b; i++) off += g_bsum[i];
        chunk_off = off;
    }
    __syncthreads();

    int excl = incl - v + (wid > 0 ? wsum[wid - 1] : 0) + chunk_off;
    if (idx < Nn + 1) {
        g_indptr[idx] = excl;
        if (idx < Nn) g_cursor[idx] = excl;
    }
}

// ---------------- fill CSR + restore zeros for next replay ----------------
__global__ void fill_k(const int* __restrict__ ei) {
    int e = blockIdx.x * blockDim.x + threadIdx.x;
    if (e < Nn + 1) g_cnt[e] = 0;
    if (e < NCHUNK) g_ready[e] = 0;
    if (e >= Ee) return;
    int s = __ldg(ei + e);
    int d = __ldg(ei + Ee + e);
    int pos = atomicAdd(g_cursor + d, 1);
    g_idx[pos] = s;
}

// ---------------- dedicated gather: one warp per node, 8-deep load pipeline ----------------
// z[gr] = hin[gr] + sum_{s in N(gr)} hin[s]. Lane owns float2 (8B); 32 lanes = full 256B row.
__global__ void __launch_bounds__(256) gather_k(const float* __restrict__ hin) {
    int wid = threadIdx.x >> 5;
    int lane = threadIdx.x & 31;
    int gr = blockIdx.x * 8 + wid;
    if (gr >= Nn) return;

    const float2* hp = reinterpret_cast<const float2*>(hin);
    float2 acc = __ldg(hp + (size_t)gr * 32 + lane);    // self
    int e = __ldg(g_indptr + gr);
    int end = __ldg(g_indptr + gr + 1);

    for (; e + 8 <= end; e += 8) {
        int s0 = __ldg(g_idx + e);
        int s1 = __ldg(g_idx + e + 1);
        int s2 = __ldg(g_idx + e + 2);
        int s3 = __ldg(g_idx + e + 3);
        int s4 = __ldg(g_idx + e + 4);
        int s5 = __ldg(g_idx + e + 5);
        int s6 = __ldg(g_idx + e + 6);
        int s7 = __ldg(g_idx + e + 7);
        float2 v0 = __ldg(hp + (size_t)s0 * 32 + lane);
        float2 v1 = __ldg(hp + (size_t)s1 * 32 + lane);
        float2 v2 = __ldg(hp + (size_t)s2 * 32 + lane);
        float2 v3 = __ldg(hp + (size_t)s3 * 32 + lane);
        float2 v4 = __ldg(hp + (size_t)s4 * 32 + lane);
        float2 v5 = __ldg(hp + (size_t)s5 * 32 + lane);
        float2 v6 = __ldg(hp + (size_t)s6 * 32 + lane);
        float2 v7 = __ldg(hp + (size_t)s7 * 32 + lane);
        acc.x += ((v0.x + v1.x) + (v2.x + v3.x)) + ((v4.x + v5.x) + (v6.x + v7.x));
        acc.y += ((v0.y + v1.y) + (v2.y + v3.y)) + ((v4.y + v5.y) + (v6.y + v7.y));
    }
    for (; e < end; e++) {
        int s = __ldg(g_idx + e);
        float2 v = __ldg(hp + (size_t)s * 32 + lane);
        acc.x += v.x; acc.y += v.y;
    }
    reinterpret_cast<float2*>(g_z)[(size_t)gr * 32 + lane] = acc;
}

// ---------------- GIN MLP (f32x2 packed) + pool-red; reads z coalesced ----------------
__global__ void __launch_bounds__(256, 5) mlp_k(float* __restrict__ hout,
                                                const int* __restrict__ batch,
                                                int layer, int write_h) {
    __shared__ __align__(16) float sZ[64][68];
    __shared__ __align__(16) float sW[64 * 64];

    int tid = threadIdx.x;
    int row0 = blockIdx.x * 64;

    // load z (coalesced)
    for (int i = tid; i < 1024; i += 256) {
        int r = i >> 4;
        int c = (i & 15) << 2;
        int gr = row0 + r;
        float4 z = make_float4(0.f, 0.f, 0.f, 0.f);
        if (gr < Nn)
            z = *reinterpret_cast<const float4*>(g_z + (size_t)gr * Hh + c);
        *reinterpret_cast<float4*>(&sZ[r][c]) = z;
    }
    {
        const float* Wg = g_W1 + layer * Hh * Hh;
        for (int i = tid * 4; i < 4096; i += 1024)
            *reinterpret_cast<float4*>(sW + i) = *reinterpret_cast<const float4*>(Wg + i);
    }
    __syncthreads();

    int tx = tid & 15;
    int ty = tid >> 4;

    u64 acc2[4][2];
    #pragma unroll
    for (int i = 0; i < 4; i++) { acc2[i][0] = 0ull; acc2[i][1] = 0ull; }

    // GEMM1
    #pragma unroll
    for (int k0 = 0; k0 < 64; k0 += 4) {
        float4 z4[4];
        #pragma unroll
        for (int i = 0; i < 4; i++)
            z4[i] = *reinterpret_cast<const float4*>(&sZ[ty * 4 + i][k0]);
        #pragma unroll
        for (int kk = 0; kk < 4; kk++) {
            ulonglong2 w2 = *reinterpret_cast<const ulonglong2*>(sW + (k0 + kk) * 64 + tx * 4);
            #pragma unroll
            for (int i = 0; i < 4; i++) {
                float zv = (kk == 0) ? z4[i].x : (kk == 1) ? z4[i].y : (kk == 2) ? z4[i].z : z4[i].w;
                u64 zp = pack2(zv);
                fma2(acc2[i][0], zp, w2.x);
                fma2(acc2[i][1], zp, w2.y);
            }
        }
    }
    float4 c1v = *reinterpret_cast<const float4*>(g_c1 + layer * Hh + tx * 4);
    __syncthreads();

    #pragma unroll
    for (int i = 0; i < 4; i++) {
        float2 a01 = unpack2(acc2[i][0]);
        float2 a23 = unpack2(acc2[i][1]);
        float4 y;
        y.x = fmaxf(a01.x + c1v.x, 0.f);
        y.y = fmaxf(a01.y + c1v.y, 0.f);
        y.z = fmaxf(a23.x + c1v.z, 0.f);
        y.w = fmaxf(a23.y + c1v.w, 0.f);
        *reinterpret_cast<float4*>(&sZ[ty * 4 + i][tx * 4]) = y;
    }
    {
        const float* Wg = g_W2 + layer * Hh * Hh;
        for (int i = tid * 4; i < 4096; i += 1024)
            *reinterpret_cast<float4*>(sW + i) = *reinterpret_cast<const float4*>(Wg + i);
    }
    __syncthreads();

    #pragma unroll
    for (int i = 0; i < 4; i++) { acc2[i][0] = 0ull; acc2[i][1] = 0ull; }

    // GEMM2
    #pragma unroll
    for (int k0 = 0; k0 < 64; k0 += 4) {
        float4 z4[4];
        #pragma unroll
        for (int i = 0; i < 4; i++)
            z4[i] = *reinterpret_cast<const float4*>(&sZ[ty * 4 + i][k0]);
        #pragma unroll
        for (int kk = 0; kk < 4; kk++) {
            ulonglong2 w2 = *reinterpret_cast<const ulonglong2*>(sW + (k0 + kk) * 64 + tx * 4);
            #pragma unroll
            for (int i = 0; i < 4; i++) {
                float zv = (kk == 0) ? z4[i].x : (kk == 1) ? z4[i].y : (kk == 2) ? z4[i].z : z4[i].w;
                u64 zp = pack2(zv);
                fma2(acc2[i][0], zp, w2.x);
                fma2(acc2[i][1], zp, w2.y);
            }
        }
    }
    float4 c2v = *reinterpret_cast<const float4*>(g_c2 + layer * Hh + tx * 4);
    #pragma unroll
    for (int i = 0; i < 4; i++) {
        int gr = row0 + ty * 4 + i;
        if (gr < Nn) {
            float2 a01 = unpack2(acc2[i][0]);
            float2 a23 = unpack2(acc2[i][1]);
            float4 y;
            y.x = fmaxf(a01.x + c2v.x, 0.f);
            y.y = fmaxf(a01.y + c2v.y, 0.f);
            y.z = fmaxf(a23.x + c2v.z, 0.f);
            y.w = fmaxf(a23.y + c2v.w, 0.f);
            if (write_h)
                *reinterpret_cast<float4*>(hout + (size_t)gr * Hh + tx * 4) = y;
            int b = __ldg(batch + gr);
            float* pp = g_pool + (size_t)b * (Ll * Hh) + layer * Hh + tx * 4;
            asm volatile("red.global.add.v4.f32 [%0], {%1,%2,%3,%4};"
                         :: "l"(pp), "f"(y.x), "f"(y.y), "f"(y.z), "f"(y.w) : "memory");
        }
    }
}

// ---------------- head (also re-zeroes g_pool for next replay) ----------------
__global__ void final_k(const float* __restrict__ W1, const float* __restrict__ b1,
                        const float* __restrict__ W2, const float* __restrict__ b2,
                        float* __restrict__ out) {
    int g = blockIdx.x;
    int j = threadIdx.x;   // 64 threads
    __shared__ float sp[Ll * Hh];
    __shared__ float sh[Hh];
    for (int i = j; i < Ll * Hh; i += 64) sp[i] = g_pool[(size_t)g * (Ll * Hh) + i];
    __syncthreads();
    *reinterpret_cast<float4*>(g_pool + (size_t)g * (Ll * Hh) + j * 4) =
        make_float4(0.f, 0.f, 0.f, 0.f);
    float a = b1[j];
    #pragma unroll 8
    for (int k = 0; k < Ll * Hh; k++) a = fmaf(sp[k], W1[k * Hh + j], a);
    sh[j] = fmaxf(a, 0.f);
    __syncthreads();
    if (j < Cc) {
        float o = b2[j];
        #pragma unroll
        for (int k = 0; k < Hh; k++) o = fmaf(sh[k], W2[k * Cc + j], o);
        out[g * Cc + j] = o;
    }
}

// ---------------- launch (gather L0 is launch #4 for ncu) ----------------
extern "C" void kernel_launch(void* const* d_in, const int* in_sizes, int n_in,
                              void* d_out, int out_size) {
    const float* x     = (const float*)d_in[0];
    const int*   ei    = (const int*)d_in[1];
    const int*   batch = (const int*)d_in[2];
    const float* cW1 = (const float*)d_in[3];
    const float* cb1 = (const float*)d_in[4];
    const float* g1  = (const float*)d_in[5];
    const float* be1 = (const float*)d_in[6];
    const float* m1  = (const float*)d_in[7];
    const float* v1  = (const float*)d_in[8];
    const float* cW2 = (const float*)d_in[9];
    const float* cb2 = (const float*)d_in[10];
    const float* g2  = (const float*)d_in[11];
    const float* be2 = (const float*)d_in[12];
    const float* m2  = (const float*)d_in[13];
    const float* v2  = (const float*)d_in[14];
    const float* l1W = (const float*)d_in[15];
    const float* l1b = (const float*)d_in[16];
    const float* l2W = (const float*)d_in[17];
    const float* l2b = (const float*)d_in[18];
    float* out = (float*)d_out;

    histfold_k<<<(Ee + 255) / 256, 256>>>(ei, cW1, cb1, g1, be1, m1, v1,
                                          cW2, cb2, g2, be2, m2, v2);
    scan_k<<<NCHUNK, 1024>>>();
    fill_k<<<(Ee + 255) / 256, 256>>>(ei);

    float* hbase;
    cudaGetSymbolAddress((void**)&hbase, g_h);

    const float* hin = x;
    for (int l = 0; l < Ll; l++) {
        gather_k<<<(Nn + 7) / 8, 256>>>(hin);
        float* hout = hbase + (size_t)l * Nn * Hh;
        mlp_k<<<(Nn + 63) / 64, 256>>>(hout, batch, l, l < Ll - 1 ? 1 : 0);
        hin = hout;
    }
    final_k<<<Gg, 64>>>(l1W, l1b, l2W, l2b, out);
}

// round 11
// speedup vs baseline: 1.5025x; 1.0469x over previous
#include <cuda_runtime.h>

#define Nn 50000
#define Ee 800000
#define Hh 64
#define Ll 4
#define Gg 500
#define Cc 10
#define BN_EPS 1e-5f
#define NCHUNK 49   // ceil((Nn+1)/1024)

typedef unsigned long long u64;

__device__ __forceinline__ u64 pack2(float v) {
    u64 r;
    asm("mov.b64 %0, {%1, %1};" : "=l"(r) : "f"(v));
    return r;
}
__device__ __forceinline__ void fma2(u64 &d, u64 a, u64 b) {
    asm("fma.rn.f32x2 %0, %1, %2, %0;" : "+l"(d) : "l"(a), "l"(b));
}
__device__ __forceinline__ float2 unpack2(u64 v) {
    float2 r;
    asm("mov.b64 {%0, %1}, %2;" : "=f"(r.x), "=f"(r.y) : "l"(v));
    return r;
}

// ---------------- device scratch ----------------
__device__ __align__(16) float g_h[(size_t)Ll * Nn * Hh];
__device__ __align__(16) float g_z[(size_t)Nn * Hh];      // gathered z = self + neighbor-sum
__device__ __align__(16) float g_W1[Ll * Hh * Hh];
__device__ __align__(16) float g_W2[Ll * Hh * Hh];
__device__ __align__(16) float g_c1[Ll * Hh];
__device__ __align__(16) float g_c2[Ll * Hh];
__device__ __align__(16) float g_pool[Gg * Ll * Hh];   // zeroed by final_k after use
// CSR by destination
__device__ int g_cnt[Nn + 1];       // zeroed by fill_k after use
__device__ int g_indptr[Nn + 1];
__device__ int g_cursor[Nn];
__device__ int g_idx[Ee];
__device__ int g_bsum[NCHUNK];
__device__ int g_ready[NCHUNK];     // zeroed by fill_k after use

// ---------------- hist (edge->dst counts) + BN fold, fused ----------------
__global__ void histfold_k(const int* __restrict__ ei,
                           const float* __restrict__ W1, const float* __restrict__ b1,
                           const float* __restrict__ g1, const float* __restrict__ be1,
                           const float* __restrict__ m1, const float* __restrict__ v1,
                           const float* __restrict__ W2, const float* __restrict__ b2,
                           const float* __restrict__ g2, const float* __restrict__ be2,
                           const float* __restrict__ m2, const float* __restrict__ v2) {
    int t = blockIdx.x * blockDim.x + threadIdx.x;
    if (t < Ll * Hh * Hh) {
        int j = t & (Hh - 1);
        int lk = t >> 6;
        int l = lk >> 6;
        int k = lk & 63;
        int lj = l * Hh + j;
        float s1 = g1[lj] * rsqrtf(v1[lj] + BN_EPS);
        float s2 = g2[lj] * rsqrtf(v2[lj] + BN_EPS);
        g_W1[t] = W1[t] * s1;
        g_W2[t] = W2[t] * s2;
        if (k == 0) {
            g_c1[lj] = b1[lj] * s1 + be1[lj] - m1[lj] * s1;
            g_c2[lj] = b2[lj] * s2 + be2[lj] - m2[lj] * s2;
        }
    }
    if (t < Ee) atomicAdd(g_cnt + __ldg(ei + Ee + t), 1);
}

// ---------------- single-kernel scan (decoupled lookback) ----------------
__global__ void scan_k() {
    __shared__ int wsum[32];
    __shared__ int chunk_off;
    int b = blockIdx.x;
    int t = threadIdx.x;
    int lane = t & 31;
    int wid = t >> 5;
    int idx = b * 1024 + t;
    int v = (idx < Nn + 1) ? g_cnt[idx] : 0;

    int incl = v;
    #pragma unroll
    for (int off = 1; off < 32; off <<= 1) {
        int n = __shfl_up_sync(0xffffffffu, incl, off);
        if (lane >= off) incl += n;
    }
    if (lane == 31) wsum[wid] = incl;
    __syncthreads();
    if (t < 32) {
        int s = wsum[t];
        #pragma unroll
        for (int off = 1; off < 32; off <<= 1) {
            int n = __shfl_up_sync(0xffffffffu, s, off);
            if (t >= off) s += n;
        }
        wsum[t] = s;
    }
    __syncthreads();

    if (t == 0) {
        g_bsum[b] = wsum[31];
        __threadfence();
        atomicExch(g_ready + b, 1);
    }
    if (t < b) {
        while (atomicAdd(g_ready + t, 0) == 0) {}
    }
    __syncthreads();
    if (t == 0) {
        int off = 0;
        for (int i = 0; i < b; i++) off += g_bsum[i];
        chunk_off = off;
    }
    __syncthreads();

    int excl = incl - v + (wid > 0 ? wsum[wid - 1] : 0) + chunk_off;
    if (idx < Nn + 1) {
        g_indptr[idx] = excl;
        if (idx < Nn) g_cursor[idx] = excl;
    }
}

// ---------------- fill CSR + restore zeros for next replay ----------------
__global__ void fill_k(const int* __restrict__ ei) {
    int e = blockIdx.x * blockDim.x + threadIdx.x;
    if (e < Nn + 1) g_cnt[e] = 0;
    if (e < NCHUNK) g_ready[e] = 0;
    if (e >= Ee) return;
    int s = __ldg(ei + e);
    int d = __ldg(ei + Ee + e);
    int pos = atomicAdd(g_cursor + d, 1);
    g_idx[pos] = s;
}

// ---------------- dedicated gather: one warp per node, 8-deep load pipeline ----------------
__global__ void __launch_bounds__(256) gather_k(const float* __restrict__ hin) {
    int wid = threadIdx.x >> 5;
    int lane = threadIdx.x & 31;
    int gr = blockIdx.x * 8 + wid;
    if (gr >= Nn) return;

    const float2* hp = reinterpret_cast<const float2*>(hin);
    float2 acc = __ldg(hp + (size_t)gr * 32 + lane);    // self
    int e = __ldg(g_indptr + gr);
    int end = __ldg(g_indptr + gr + 1);

    for (; e + 8 <= end; e += 8) {
        int s0 = __ldg(g_idx + e);
        int s1 = __ldg(g_idx + e + 1);
        int s2 = __ldg(g_idx + e + 2);
        int s3 = __ldg(g_idx + e + 3);
        int s4 = __ldg(g_idx + e + 4);
        int s5 = __ldg(g_idx + e + 5);
        int s6 = __ldg(g_idx + e + 6);
        int s7 = __ldg(g_idx + e + 7);
        float2 v0 = __ldg(hp + (size_t)s0 * 32 + lane);
        float2 v1 = __ldg(hp + (size_t)s1 * 32 + lane);
        float2 v2 = __ldg(hp + (size_t)s2 * 32 + lane);
        float2 v3 = __ldg(hp + (size_t)s3 * 32 + lane);
        float2 v4 = __ldg(hp + (size_t)s4 * 32 + lane);
        float2 v5 = __ldg(hp + (size_t)s5 * 32 + lane);
        float2 v6 = __ldg(hp + (size_t)s6 * 32 + lane);
        float2 v7 = __ldg(hp + (size_t)s7 * 32 + lane);
        acc.x += ((v0.x + v1.x) + (v2.x + v3.x)) + ((v4.x + v5.x) + (v6.x + v7.x));
        acc.y += ((v0.y + v1.y) + (v2.y + v3.y)) + ((v4.y + v5.y) + (v6.y + v7.y));
    }
    for (; e < end; e++) {
        int s = __ldg(g_idx + e);
        float2 v = __ldg(hp + (size_t)s * 32 + lane);
        acc.x += v.x; acc.y += v.y;
    }
    reinterpret_cast<float2*>(g_z)[(size_t)gr * 32 + lane] = acc;
}

// ---------------- GIN MLP: 128 thr/CTA, 64-row tile, 4 rows x 8 cols per thread ----------
// Thread (tx = tid&7, ty = tid>>3): rows {ty+16i}, cols {4tx..4tx+3} and {32+4tx..+3}.
// Conflict-free: w reads = 8 distinct banks x16B (full wavefronts); z rows interleaved
// by 16 so bank = 4ty+k0 (stride 68 => 16*68 = 0 mod 32).
__global__ void __launch_bounds__(128, 6) mlp_k(float* __restrict__ hout,
                                                const int* __restrict__ batch,
                                                int layer, int write_h) {
    __shared__ __align__(16) float sZ[64][68];
    __shared__ __align__(16) float sW[64 * 64];

    int tid = threadIdx.x;
    int row0 = blockIdx.x * 64;

    // load z (coalesced): 1024 float4 over 128 threads
    for (int i = tid; i < 1024; i += 128) {
        int r = i >> 4;
        int c = (i & 15) << 2;
        int gr = row0 + r;
        float4 z = make_float4(0.f, 0.f, 0.f, 0.f);
        if (gr < Nn)
            z = *reinterpret_cast<const float4*>(g_z + (size_t)gr * Hh + c);
        *reinterpret_cast<float4*>(&sZ[r][c]) = z;
    }
    {
        const float* Wg = g_W1 + layer * Hh * Hh;
        for (int i = tid * 4; i < 4096; i += 512)
            *reinterpret_cast<float4*>(sW + i) = *reinterpret_cast<const float4*>(Wg + i);
    }
    __syncthreads();

    int tx = tid & 7;
    int ty = tid >> 3;    // 0..15

    u64 acc2[4][4];   // [row i][col-pair j]: cols {4tx,4tx+1},{4tx+2,+3},{32+4tx,+1},{32+4tx+2,+3}
    #pragma unroll
    for (int i = 0; i < 4; i++)
        #pragma unroll
        for (int j = 0; j < 4; j++) acc2[i][j] = 0ull;

    // GEMM1
    #pragma unroll
    for (int k0 = 0; k0 < 64; k0 += 4) {
        float4 z4[4];
        #pragma unroll
        for (int i = 0; i < 4; i++)
            z4[i] = *reinterpret_cast<const float4*>(&sZ[ty + 16 * i][k0]);
        #pragma unroll
        for (int kk = 0; kk < 4; kk++) {
            ulonglong2 wa = *reinterpret_cast<const ulonglong2*>(sW + (k0 + kk) * 64 + tx * 4);
            ulonglong2 wb = *reinterpret_cast<const ulonglong2*>(sW + (k0 + kk) * 64 + 32 + tx * 4);
            #pragma unroll
            for (int i = 0; i < 4; i++) {
                float zv = (kk == 0) ? z4[i].x : (kk == 1) ? z4[i].y : (kk == 2) ? z4[i].z : z4[i].w;
                u64 zp = pack2(zv);
                fma2(acc2[i][0], zp, wa.x);
                fma2(acc2[i][1], zp, wa.y);
                fma2(acc2[i][2], zp, wb.x);
                fma2(acc2[i][3], zp, wb.y);
            }
        }
    }
    float4 c1a = *reinterpret_cast<const float4*>(g_c1 + layer * Hh + tx * 4);
    float4 c1b = *reinterpret_cast<const float4*>(g_c1 + layer * Hh + 32 + tx * 4);
    __syncthreads();

    // y1 = relu(acc + c1) -> sZ; reload sW with W2'
    #pragma unroll
    for (int i = 0; i < 4; i++) {
        int r = ty + 16 * i;
        float2 a0 = unpack2(acc2[i][0]);
        float2 a1 = unpack2(acc2[i][1]);
        float2 a2 = unpack2(acc2[i][2]);
        float2 a3 = unpack2(acc2[i][3]);
        float4 ya, yb;
        ya.x = fmaxf(a0.x + c1a.x, 0.f);
        ya.y = fmaxf(a0.y + c1a.y, 0.f);
        ya.z = fmaxf(a1.x + c1a.z, 0.f);
        ya.w = fmaxf(a1.y + c1a.w, 0.f);
        yb.x = fmaxf(a2.x + c1b.x, 0.f);
        yb.y = fmaxf(a2.y + c1b.y, 0.f);
        yb.z = fmaxf(a3.x + c1b.z, 0.f);
        yb.w = fmaxf(a3.y + c1b.w, 0.f);
        *reinterpret_cast<float4*>(&sZ[r][tx * 4]) = ya;
        *reinterpret_cast<float4*>(&sZ[r][32 + tx * 4]) = yb;
    }
    {
        const float* Wg = g_W2 + layer * Hh * Hh;
        for (int i = tid * 4; i < 4096; i += 512)
            *reinterpret_cast<float4*>(sW + i) = *reinterpret_cast<const float4*>(Wg + i);
    }
    __syncthreads();

    #pragma unroll
    for (int i = 0; i < 4; i++)
        #pragma unroll
        for (int j = 0; j < 4; j++) acc2[i][j] = 0ull;

    // GEMM2
    #pragma unroll
    for (int k0 = 0; k0 < 64; k0 += 4) {
        float4 z4[4];
        #pragma unroll
        for (int i = 0; i < 4; i++)
            z4[i] = *reinterpret_cast<const float4*>(&sZ[ty + 16 * i][k0]);
        #pragma unroll
        for (int kk = 0; kk < 4; kk++) {
            ulonglong2 wa = *reinterpret_cast<const ulonglong2*>(sW + (k0 + kk) * 64 + tx * 4);
            ulonglong2 wb = *reinterpret_cast<const ulonglong2*>(sW + (k0 + kk) * 64 + 32 + tx * 4);
            #pragma unroll
            for (int i = 0; i < 4; i++) {
                float zv = (kk == 0) ? z4[i].x : (kk == 1) ? z4[i].y : (kk == 2) ? z4[i].z : z4[i].w;
                u64 zp = pack2(zv);
                fma2(acc2[i][0], zp, wa.x);
                fma2(acc2[i][1], zp, wa.y);
                fma2(acc2[i][2], zp, wb.x);
                fma2(acc2[i][3], zp, wb.y);
            }
        }
    }
    float4 c2a = *reinterpret_cast<const float4*>(g_c2 + layer * Hh + tx * 4);
    float4 c2b = *reinterpret_cast<const float4*>(g_c2 + layer * Hh + 32 + tx * 4);
    #pragma unroll
    for (int i = 0; i < 4; i++) {
        int gr = row0 + ty + 16 * i;
        if (gr < Nn) {
            float2 a0 = unpack2(acc2[i][0]);
            float2 a1 = unpack2(acc2[i][1]);
            float2 a2 = unpack2(acc2[i][2]);
            float2 a3 = unpack2(acc2[i][3]);
            float4 ya, yb;
            ya.x = fmaxf(a0.x + c2a.x, 0.f);
            ya.y = fmaxf(a0.y + c2a.y, 0.f);
            ya.z = fmaxf(a1.x + c2a.z, 0.f);
            ya.w = fmaxf(a1.y + c2a.w, 0.f);
            yb.x = fmaxf(a2.x + c2b.x, 0.f);
            yb.y = fmaxf(a2.y + c2b.y, 0.f);
            yb.z = fmaxf(a3.x + c2b.z, 0.f);
            yb.w = fmaxf(a3.y + c2b.w, 0.f);
            if (write_h) {
                *reinterpret_cast<float4*>(hout + (size_t)gr * Hh + tx * 4) = ya;
                *reinterpret_cast<float4*>(hout + (size_t)gr * Hh + 32 + tx * 4) = yb;
            }
            int b = __ldg(batch + gr);
            float* pa = g_pool + (size_t)b * (Ll * Hh) + layer * Hh + tx * 4;
            float* pb = pa + 32;
            asm volatile("red.global.add.v4.f32 [%0], {%1,%2,%3,%4};"
                         :: "l"(pa), "f"(ya.x), "f"(ya.y), "f"(ya.z), "f"(ya.w) : "memory");
            asm volatile("red.global.add.v4.f32 [%0], {%1,%2,%3,%4};"
                         :: "l"(pb), "f"(yb.x), "f"(yb.y), "f"(yb.z), "f"(yb.w) : "memory");
        }
    }
}

// ---------------- head (also re-zeroes g_pool for next replay) ----------------
__global__ void final_k(const float* __restrict__ W1, const float* __restrict__ b1,
                        const float* __restrict__ W2, const float* __restrict__ b2,
                        float* __restrict__ out) {
    int g = blockIdx.x;
    int j = threadIdx.x;   // 64 threads
    __shared__ float sp[Ll * Hh];
    __shared__ float sh[Hh];
    for (int i = j; i < Ll * Hh; i += 64) sp[i] = g_pool[(size_t)g * (Ll * Hh) + i];
    __syncthreads();
    *reinterpret_cast<float4*>(g_pool + (size_t)g * (Ll * Hh) + j * 4) =
        make_float4(0.f, 0.f, 0.f, 0.f);
    float a = b1[j];
    #pragma unroll 8
    for (int k = 0; k < Ll * Hh; k++) a = fmaf(sp[k], W1[k * Hh + j], a);
    sh[j] = fmaxf(a, 0.f);
    __syncthreads();
    if (j < Cc) {
        float o = b2[j];
        #pragma unroll
        for (int k = 0; k < Hh; k++) o = fmaf(sh[k], W2[k * Cc + j], o);
        out[g * Cc + j] = o;
    }
}

// ---------------- launch (mlp L0 is launch #5; gather L0 is #4) ----------------
extern "C" void kernel_launch(void* const* d_in, const int* in_sizes, int n_in,
                              void* d_out, int out_size) {
    const float* x     = (const float*)d_in[0];
    const int*   ei    = (const int*)d_in[1];
    const int*   batch = (const int*)d_in[2];
    const float* cW1 = (const float*)d_in[3];
    const float* cb1 = (const float*)d_in[4];
    const float* g1  = (const float*)d_in[5];
    const float* be1 = (const float*)d_in[6];
    const float* m1  = (const float*)d_in[7];
    const float* v1  = (const float*)d_in[8];
    const float* cW2 = (const float*)d_in[9];
    const float* cb2 = (const float*)d_in[10];
    const float* g2  = (const float*)d_in[11];
    const float* be2 = (const float*)d_in[12];
    const float* m2  = (const float*)d_in[13];
    const float* v2  = (const float*)d_in[14];
    const float* l1W = (const float*)d_in[15];
    const float* l1b = (const float*)d_in[16];
    const float* l2W = (const float*)d_in[17];
    const float* l2b = (const float*)d_in[18];
    float* out = (float*)d_out;

    histfold_k<<<(Ee + 255) / 256, 256>>>(ei, cW1, cb1, g1, be1, m1, v1,
                                          cW2, cb2, g2, be2, m2, v2);
    scan_k<<<NCHUNK, 1024>>>();
    fill_k<<<(Ee + 255) / 256, 256>>>(ei);

    float* hbase;
    cudaGetSymbolAddress((void**)&hbase, g_h);

    const float* hin = x;
    for (int l = 0; l < Ll; l++) {
        gather_k<<<(Nn + 7) / 8, 256>>>(hin);
        float* hout = hbase + (size_t)l * Nn * Hh;
        mlp_k<<<(Nn + 63) / 64, 128>>>(hout, batch, l, l < Ll - 1 ? 1 : 0);
        hin = hout;
    }
    final_k<<<Gg, 64>>>(l1W, l1b, l2W, l2b, out);
}

// round 12
// speedup vs baseline: 1.5364x; 1.0226x over previous
#include <cuda_runtime.h>

#define Nn 50000
#define Ee 800000
#define Hh 64
#define Ll 4
#define Gg 500
#define Cc 10
#define BN_EPS 1e-5f
#define NCHUNK 49   // ceil((Nn+1)/1024)

typedef unsigned long long u64;

__device__ __forceinline__ u64 pack2(float v) {
    u64 r;
    asm("mov.b64 %0, {%1, %1};" : "=l"(r) : "f"(v));
    return r;
}
__device__ __forceinline__ void fma2(u64 &d, u64 a, u64 b) {
    asm("fma.rn.f32x2 %0, %1, %2, %0;" : "+l"(d) : "l"(a), "l"(b));
}
__device__ __forceinline__ float2 unpack2(u64 v) {
    float2 r;
    asm("mov.b64 {%0, %1}, %2;" : "=f"(r.x), "=f"(r.y) : "l"(v));
    return r;
}

// ---------------- device scratch ----------------
__device__ __align__(16) float g_h[(size_t)Ll * Nn * Hh];
__device__ __align__(16) float g_z[(size_t)Nn * Hh];      // gathered z = self + neighbor-sum
__device__ __align__(16) float g_W1[Ll * Hh * Hh];
__device__ __align__(16) float g_W2[Ll * Hh * Hh];
__device__ __align__(16) float g_c1[Ll * Hh];
__device__ __align__(16) float g_c2[Ll * Hh];
__device__ __align__(16) float g_pool[Gg * Ll * Hh];   // zeroed by zeropool_k each call
// CSR by destination
__device__ int g_cnt[Nn + 1];       // zeroed by fill_k after use
__device__ int g_indptr[Nn + 1];
__device__ int g_cursor[Nn];
__device__ int g_idx[Ee];
__device__ int g_bsum[NCHUNK];
__device__ int g_ready[NCHUNK];     // zeroed by fill_k after use

// ---------------- hist (edge->dst counts) + BN fold, fused ----------------
__global__ void histfold_k(const int* __restrict__ ei,
                           const float* __restrict__ W1, const float* __restrict__ b1,
                           const float* __restrict__ g1, const float* __restrict__ be1,
                           const float* __restrict__ m1, const float* __restrict__ v1,
                           const float* __restrict__ W2, const float* __restrict__ b2,
                           const float* __restrict__ g2, const float* __restrict__ be2,
                           const float* __restrict__ m2, const float* __restrict__ v2) {
    int t = blockIdx.x * blockDim.x + threadIdx.x;
    if (t < Ll * Hh * Hh) {
        int j = t & (Hh - 1);
        int lk = t >> 6;
        int l = lk >> 6;
        int k = lk & 63;
        int lj = l * Hh + j;
        float s1 = g1[lj] * rsqrtf(v1[lj] + BN_EPS);
        float s2 = g2[lj] * rsqrtf(v2[lj] + BN_EPS);
        g_W1[t] = W1[t] * s1;
        g_W2[t] = W2[t] * s2;
        if (k == 0) {
            g_c1[lj] = b1[lj] * s1 + be1[lj] - m1[lj] * s1;
            g_c2[lj] = b2[lj] * s2 + be2[lj] - m2[lj] * s2;
        }
    }
    if (t < Ee) atomicAdd(g_cnt + __ldg(ei + Ee + t), 1);
}

// ---------------- single-kernel scan (decoupled lookback) ----------------
__global__ void scan_k() {
    __shared__ int wsum[32];
    __shared__ int chunk_off;
    int b = blockIdx.x;
    int t = threadIdx.x;
    int lane = t & 31;
    int wid = t >> 5;
    int idx = b * 1024 + t;
    int v = (idx < Nn + 1) ? g_cnt[idx] : 0;

    int incl = v;
    #pragma unroll
    for (int off = 1; off < 32; off <<= 1) {
        int n = __shfl_up_sync(0xffffffffu, incl, off);
        if (lane >= off) incl += n;
    }
    if (lane == 31) wsum[wid] = incl;
    __syncthreads();
    if (t < 32) {
        int s = wsum[t];
        #pragma unroll
        for (int off = 1; off < 32; off <<= 1) {
            int n = __shfl_up_sync(0xffffffffu, s, off);
            if (t >= off) s += n;
        }
        wsum[t] = s;
    }
    __syncthreads();

    if (t == 0) {
        g_bsum[b] = wsum[31];
        __threadfence();
        atomicExch(g_ready + b, 1);
    }
    if (t < b) {
        while (atomicAdd(g_ready + t, 0) == 0) {}
    }
    __syncthreads();
    if (t == 0) {
        int off = 0;
        for (int i = 0; i < b; i++) off += g_bsum[i];
        chunk_off = off;
    }
    __syncthreads();

    int excl = incl - v + (wid > 0 ? wsum[wid - 1] : 0) + chunk_off;
    if (idx < Nn + 1) {
        g_indptr[idx] = excl;
        if (idx < Nn) g_cursor[idx] = excl;
    }
}

// ---------------- fill CSR + restore zeros for next replay ----------------
__global__ void fill_k(const int* __restrict__ ei) {
    int e = blockIdx.x * blockDim.x + threadIdx.x;
    if (e < Nn + 1) g_cnt[e] = 0;
    if (e < NCHUNK) g_ready[e] = 0;
    if (e >= Ee) return;
    int s = __ldg(ei + e);
    int d = __ldg(ei + Ee + e);
    int pos = atomicAdd(g_cursor + d, 1);
    g_idx[pos] = s;
}

// ---------------- zero pool (launch #4 -> pushes mlp L0 to launch #6 for ncu) ---------
__global__ void zeropool_k() {
    int t = blockIdx.x * blockDim.x + threadIdx.x;
    if (t < Gg * Ll * Hh / 4)
        reinterpret_cast<float4*>(g_pool)[t] = make_float4(0.f, 0.f, 0.f, 0.f);
}

// ---------------- dedicated gather: one warp per node, 8-deep load pipeline ----------------
__global__ void __launch_bounds__(256) gather_k(const float* __restrict__ hin) {
    int wid = threadIdx.x >> 5;
    int lane = threadIdx.x & 31;
    int gr = blockIdx.x * 8 + wid;
    if (gr >= Nn) return;

    const float2* hp = reinterpret_cast<const float2*>(hin);
    float2 acc = __ldg(hp + (size_t)gr * 32 + lane);    // self
    int e = __ldg(g_indptr + gr);
    int end = __ldg(g_indptr + gr + 1);

    for (; e + 8 <= end; e += 8) {
        int s0 = __ldg(g_idx + e);
        int s1 = __ldg(g_idx + e + 1);
        int s2 = __ldg(g_idx + e + 2);
        int s3 = __ldg(g_idx + e + 3);
        int s4 = __ldg(g_idx + e + 4);
        int s5 = __ldg(g_idx + e + 5);
        int s6 = __ldg(g_idx + e + 6);
        int s7 = __ldg(g_idx + e + 7);
        float2 v0 = __ldg(hp + (size_t)s0 * 32 + lane);
        float2 v1 = __ldg(hp + (size_t)s1 * 32 + lane);
        float2 v2 = __ldg(hp + (size_t)s2 * 32 + lane);
        float2 v3 = __ldg(hp + (size_t)s3 * 32 + lane);
        float2 v4 = __ldg(hp + (size_t)s4 * 32 + lane);
        float2 v5 = __ldg(hp + (size_t)s5 * 32 + lane);
        float2 v6 = __ldg(hp + (size_t)s6 * 32 + lane);
        float2 v7 = __ldg(hp + (size_t)s7 * 32 + lane);
        acc.x += ((v0.x + v1.x) + (v2.x + v3.x)) + ((v4.x + v5.x) + (v6.x + v7.x));
        acc.y += ((v0.y + v1.y) + (v2.y + v3.y)) + ((v4.y + v5.y) + (v6.y + v7.y));
    }
    for (; e < end; e++) {
        int s = __ldg(g_idx + e);
        float2 v = __ldg(hp + (size_t)s * 32 + lane);
        acc.x += v.x; acc.y += v.y;
    }
    reinterpret_cast<float2*>(g_z)[(size_t)gr * 32 + lane] = acc;
}

// ---------------- GIN MLP: 256 thr/CTA, 128-row tile, 4 rows x 8 cols per thread ----------
// tx = tid&7 -> cols {4tx..4tx+3} and {32+4tx..+3}; ty = tid>>3 (0..31) -> rows {ty+32i}.
// Conflict-free: w reads broadcast over ty (8 lanes x 16B = 128B wavefronts);
// z float4 reads broadcast over tx, 4 row-addresses at banks 4*ty (stride 68).
__global__ void __launch_bounds__(256, 3) mlp_k(float* __restrict__ hout,
                                                const int* __restrict__ batch,
                                                int layer, int write_h) {
    __shared__ __align__(16) float sZ[128][68];
    __shared__ __align__(16) float sW[64 * 64];

    int tid = threadIdx.x;
    int row0 = blockIdx.x * 128;

    // load z (coalesced): 2048 float4 over 256 threads
    for (int i = tid; i < 2048; i += 256) {
        int r = i >> 4;
        int c = (i & 15) << 2;
        int gr = row0 + r;
        float4 z = make_float4(0.f, 0.f, 0.f, 0.f);
        if (gr < Nn)
            z = *reinterpret_cast<const float4*>(g_z + (size_t)gr * Hh + c);
        *reinterpret_cast<float4*>(&sZ[r][c]) = z;
    }
    {
        const float* Wg = g_W1 + layer * Hh * Hh;
        for (int i = tid * 4; i < 4096; i += 1024)
            *reinterpret_cast<float4*>(sW + i) = *reinterpret_cast<const float4*>(Wg + i);
    }
    __syncthreads();

    int tx = tid & 7;
    int ty = tid >> 3;    // 0..31

    u64 acc2[4][4];
    #pragma unroll
    for (int i = 0; i < 4; i++)
        #pragma unroll
        for (int j = 0; j < 4; j++) acc2[i][j] = 0ull;

    // GEMM1
    #pragma unroll
    for (int k0 = 0; k0 < 64; k0 += 4) {
        float4 z4[4];
        #pragma unroll
        for (int i = 0; i < 4; i++)
            z4[i] = *reinterpret_cast<const float4*>(&sZ[ty + 32 * i][k0]);
        #pragma unroll
        for (int kk = 0; kk < 4; kk++) {
            ulonglong2 wa = *reinterpret_cast<const ulonglong2*>(sW + (k0 + kk) * 64 + tx * 4);
            ulonglong2 wb = *reinterpret_cast<const ulonglong2*>(sW + (k0 + kk) * 64 + 32 + tx * 4);
            #pragma unroll
            for (int i = 0; i < 4; i++) {
                float zv = (kk == 0) ? z4[i].x : (kk == 1) ? z4[i].y : (kk == 2) ? z4[i].z : z4[i].w;
                u64 zp = pack2(zv);
                fma2(acc2[i][0], zp, wa.x);
                fma2(acc2[i][1], zp, wa.y);
                fma2(acc2[i][2], zp, wb.x);
                fma2(acc2[i][3], zp, wb.y);
            }
        }
    }
    float4 c1a = *reinterpret_cast<const float4*>(g_c1 + layer * Hh + tx * 4);
    float4 c1b = *reinterpret_cast<const float4*>(g_c1 + layer * Hh + 32 + tx * 4);
    __syncthreads();

    // y1 = relu(acc + c1) -> sZ; reload sW with W2'
    #pragma unroll
    for (int i = 0; i < 4; i++) {
        int r = ty + 32 * i;
        float2 a0 = unpack2(acc2[i][0]);
        float2 a1 = unpack2(acc2[i][1]);
        float2 a2 = unpack2(acc2[i][2]);
        float2 a3 = unpack2(acc2[i][3]);
        float4 ya, yb;
        ya.x = fmaxf(a0.x + c1a.x, 0.f);
        ya.y = fmaxf(a0.y + c1a.y, 0.f);
        ya.z = fmaxf(a1.x + c1a.z, 0.f);
        ya.w = fmaxf(a1.y + c1a.w, 0.f);
        yb.x = fmaxf(a2.x + c1b.x, 0.f);
        yb.y = fmaxf(a2.y + c1b.y, 0.f);
        yb.z = fmaxf(a3.x + c1b.z, 0.f);
        yb.w = fmaxf(a3.y + c1b.w, 0.f);
        *reinterpret_cast<float4*>(&sZ[r][tx * 4]) = ya;
        *reinterpret_cast<float4*>(&sZ[r][32 + tx * 4]) = yb;
    }
    {
        const float* Wg = g_W2 + layer * Hh * Hh;
        for (int i = tid * 4; i < 4096; i += 1024)
            *reinterpret_cast<float4*>(sW + i) = *reinterpret_cast<const float4*>(Wg + i);
    }
    __syncthreads();

    #pragma unroll
    for (int i = 0; i < 4; i++)
        #pragma unroll
        for (int j = 0; j < 4; j++) acc2[i][j] = 0ull;

    // GEMM2
    #pragma unroll
    for (int k0 = 0; k0 < 64; k0 += 4) {
        float4 z4[4];
        #pragma unroll
        for (int i = 0; i < 4; i++)
            z4[i] = *reinterpret_cast<const float4*>(&sZ[ty + 32 * i][k0]);
        #pragma unroll
        for (int kk = 0; kk < 4; kk++) {
            ulonglong2 wa = *reinterpret_cast<const ulonglong2*>(sW + (k0 + kk) * 64 + tx * 4);
            ulonglong2 wb = *reinterpret_cast<const ulonglong2*>(sW + (k0 + kk) * 64 + 32 + tx * 4);
            #pragma unroll
            for (int i = 0; i < 4; i++) {
                float zv = (kk == 0) ? z4[i].x : (kk == 1) ? z4[i].y : (kk == 2) ? z4[i].z : z4[i].w;
                u64 zp = pack2(zv);
                fma2(acc2[i][0], zp, wa.x);
                fma2(acc2[i][1], zp, wa.y);
                fma2(acc2[i][2], zp, wb.x);
                fma2(acc2[i][3], zp, wb.y);
            }
        }
    }
    float4 c2a = *reinterpret_cast<const float4*>(g_c2 + layer * Hh + tx * 4);
    float4 c2b = *reinterpret_cast<const float4*>(g_c2 + layer * Hh + 32 + tx * 4);
    #pragma unroll
    for (int i = 0; i < 4; i++) {
        int gr = row0 + ty + 32 * i;
        if (gr < Nn) {
            float2 a0 = unpack2(acc2[i][0]);
            float2 a1 = unpack2(acc2[i][1]);
            float2 a2 = unpack2(acc2[i][2]);
            float2 a3 = unpack2(acc2[i][3]);
            float4 ya, yb;
            ya.x = fmaxf(a0.x + c2a.x, 0.f);
            ya.y = fmaxf(a0.y + c2a.y, 0.f);
            ya.z = fmaxf(a1.x + c2a.z, 0.f);
            ya.w = fmaxf(a1.y + c2a.w, 0.f);
            yb.x = fmaxf(a2.x + c2b.x, 0.f);
            yb.y = fmaxf(a2.y + c2b.y, 0.f);
            yb.z = fmaxf(a3.x + c2b.z, 0.f);
            yb.w = fmaxf(a3.y + c2b.w, 0.f);
            if (write_h) {
                *reinterpret_cast<float4*>(hout + (size_t)gr * Hh + tx * 4) = ya;
                *reinterpret_cast<float4*>(hout + (size_t)gr * Hh + 32 + tx * 4) = yb;
            }
            int b = __ldg(batch + gr);
            float* pa = g_pool + (size_t)b * (Ll * Hh) + layer * Hh + tx * 4;
            float* pb = pa + 32;
            asm volatile("red.global.add.v4.f32 [%0], {%1,%2,%3,%4};"
                         :: "l"(pa), "f"(ya.x), "f"(ya.y), "f"(ya.z), "f"(ya.w) : "memory");
            asm volatile("red.global.add.v4.f32 [%0], {%1,%2,%3,%4};"
                         :: "l"(pb), "f"(yb.x), "f"(yb.y), "f"(yb.z), "f"(yb.w) : "memory");
        }
    }
}

// ---------------- head ----------------
__global__ void final_k(const float* __restrict__ W1, const float* __restrict__ b1,
                        const float* __restrict__ W2, const float* __restrict__ b2,
                        float* __restrict__ out) {
    int g = blockIdx.x;
    int j = threadIdx.x;   // 64 threads
    __shared__ float sp[Ll * Hh];
    __shared__ float sh[Hh];
    for (int i = j; i < Ll * Hh; i += 64) sp[i] = g_pool[(size_t)g * (Ll * Hh) + i];
    __syncthreads();
    float a = b1[j];
    #pragma unroll 8
    for (int k = 0; k < Ll * Hh; k++) a = fmaf(sp[k], W1[k * Hh + j], a);
    sh[j] = fmaxf(a, 0.f);
    __syncthreads();
    if (j < Cc) {
        float o = b2[j];
        #pragma unroll
        for (int k = 0; k < Hh; k++) o = fmaf(sh[k], W2[k * Cc + j], o);
        out[g * Cc + j] = o;
    }
}

// ---------------- launch (#6 = mlp L0 for ncu capture) ----------------
extern "C" void kernel_launch(void* const* d_in, const int* in_sizes, int n_in,
                              void* d_out, int out_size) {
    const float* x     = (const float*)d_in[0];
    const int*   ei    = (const int*)d_in[1];
    const int*   batch = (const int*)d_in[2];
    const float* cW1 = (const float*)d_in[3];
    const float* cb1 = (const float*)d_in[4];
    const float* g1  = (const float*)d_in[5];
    const float* be1 = (const float*)d_in[6];
    const float* m1  = (const float*)d_in[7];
    const float* v1  = (const float*)d_in[8];
    const float* cW2 = (const float*)d_in[9];
    const float* cb2 = (const float*)d_in[10];
    const float* g2  = (const float*)d_in[11];
    const float* be2 = (const float*)d_in[12];
    const float* m2  = (const float*)d_in[13];
    const float* v2  = (const float*)d_in[14];
    const float* l1W = (const float*)d_in[15];
    const float* l1b = (const float*)d_in[16];
    const float* l2W = (const float*)d_in[17];
    const float* l2b = (const float*)d_in[18];
    float* out = (float*)d_out;

    histfold_k<<<(Ee + 255) / 256, 256>>>(ei, cW1, cb1, g1, be1, m1, v1,
                                          cW2, cb2, g2, be2, m2, v2);   // 1
    scan_k<<<NCHUNK, 1024>>>();                                         // 2
    fill_k<<<(Ee + 255) / 256, 256>>>(ei);                              // 3
    zeropool_k<<<(Gg * Ll * Hh / 4 + 255) / 256, 256>>>();              // 4

    float* hbase;
    cudaGetSymbolAddress((void**)&hbase, g_h);

    const float* hin = x;
    for (int l = 0; l < Ll; l++) {
        gather_k<<<(Nn + 7) / 8, 256>>>(hin);                           // 5, 7, 9, 11
        float* hout = hbase + (size_t)l * Nn * Hh;
        mlp_k<<<(Nn + 127) / 128, 256>>>(hout, batch, l, l < Ll - 1 ? 1 : 0); // 6, 8, 10, 12
        hin = hout;
    }
    final_k<<<Gg, 64>>>(l1W, l1b, l2W, l2b, out);
}